// round 12
// baseline (speedup 1.0000x reference)
#include <cuda_runtime.h>
#include <cuda_bf16.h>
#include <math.h>
#include <stdint.h>

// Problem constants
#define NK    8192
#define DD    256
#define NTOK  32768
#define HWSZ  4096
#define ZELEMS 8388608

// Output layout offsets (float32, reference return order)
#define OFF_ZST  0
#define OFF_IDX  8388608
#define OFF_ZQ   8421376
#define OFF_EMB  16809984
#define OFF_CS   18907136
#define OFF_AVG  18915328

#define NSLICE 8
#define KSLICE 1024
#define NTILE64 512       // NTOK / 64

// Scratch (__device__ globals)
__device__ float g_Ahi[NTOK * DD];
__device__ float g_Alo[NTOK * DD];
__device__ float g_Bhi[NK * DD];
__device__ float g_Blo[NK * DD];
__device__ float g_nAh2[NTOK];
__device__ float g_nAl2[NTOK];
__device__ int   g_maxBlBits;
__device__ float2 g_pv[NTILE64 * NSLICE * 64];   // (V1, V2)
__device__ int    g_pi[NTILE64 * NSLICE * 64];   // I1
__device__ int   g_flagCnt;
__device__ int   g_flagTok[NTOK];
__device__ float g_rv[NTOK * 8];
__device__ int   g_ri[NTOK * 8];
__device__ int   g_idx[NTOK];

// ============================================================================
// helpers
// ============================================================================
__device__ __forceinline__ uint32_t smem_to_u32(const void* p) {
    uint32_t a;
    asm("{ .reg .u64 t; cvta.to.shared.u64 t, %1; cvt.u32.u64 %0, t; }" : "=r"(a) : "l"(p));
    return a;
}
__device__ __forceinline__ void cpasync16(uint32_t dst, const void* src) {
    asm volatile("cp.async.cg.shared.global [%0], [%1], 16;" :: "r"(dst), "l"(src));
}
#define CPASYNC_COMMIT() asm volatile("cp.async.commit_group;" ::: "memory")
#define CPASYNC_WAIT(n)  asm volatile("cp.async.wait_group %0;" :: "n"(n) : "memory")

__device__ __forceinline__ float tf32_rna(float x) {
    uint32_t u;
    asm("cvt.rna.tf32.f32 %0, %1;" : "=r"(u) : "f"(x));
    return __uint_as_float(u);
}

__device__ __forceinline__ void mma8(float* c, const float* a, const float* b) {
    asm volatile(
        "mma.sync.aligned.m16n8k8.row.col.f32.tf32.tf32.f32 "
        "{%0,%1,%2,%3}, {%4,%5,%6,%7}, {%8,%9}, {%0,%1,%2,%3};"
        : "+f"(c[0]), "+f"(c[1]), "+f"(c[2]), "+f"(c[3])
        : "r"(__float_as_uint(a[0])), "r"(__float_as_uint(a[1])),
          "r"(__float_as_uint(a[2])), "r"(__float_as_uint(a[3])),
          "r"(__float_as_uint(b[0])), "r"(__float_as_uint(b[1])));
}

// permuted column position within 8-groups: p=(c&3)*2+(c>>2)
__device__ __forceinline__ int dperm(int c) {
    int inner = c & 7;
    return (c & ~7) + ((inner & 3) * 2) + (inner >> 2);
}

// ============================================================================
// init
// ============================================================================
__global__ void init_kernel(const float* __restrict__ cluster_size,
                            const float* __restrict__ embed_avg,
                            float* __restrict__ cs_out,
                            float* __restrict__ avg_out) {
    int t = blockIdx.x * blockDim.x + threadIdx.x;
    if (t < NK) cs_out[t] = 0.99f * cluster_size[t];
    if (t < NK * DD) avg_out[t] = 0.99f * embed_avg[t];
    if (t == 0) { g_maxBlBits = 0; g_flagCnt = 0; }
}

// ============================================================================
// Row L2-normalize (final new_embedding). One warp per row.
// ============================================================================
__global__ void norm_rows_kernel(const float* __restrict__ in,
                                 float* __restrict__ out, int nrows) {
    int warp = (blockIdx.x * blockDim.x + threadIdx.x) >> 5;
    int lane = threadIdx.x & 31;
    if (warp >= nrows) return;
    const float4* ip = reinterpret_cast<const float4*>(in + (size_t)warp * DD);
    float4 v0 = ip[lane];
    float4 v1 = ip[lane + 32];
    float s = v0.x*v0.x + v0.y*v0.y + v0.z*v0.z + v0.w*v0.w
            + v1.x*v1.x + v1.y*v1.y + v1.z*v1.z + v1.w*v1.w;
    #pragma unroll
    for (int off = 16; off > 0; off >>= 1) s += __shfl_xor_sync(0xFFFFFFFFu, s, off);
    float nrm = fmaxf(sqrtf(s), 1e-12f);
    float4 o0, o1;
    o0.x = v0.x/nrm; o0.y = v0.y/nrm; o0.z = v0.z/nrm; o0.w = v0.w/nrm;
    o1.x = v1.x/nrm; o1.y = v1.y/nrm; o1.z = v1.z/nrm; o1.w = v1.w/nrm;
    float4* op = reinterpret_cast<float4*>(out + (size_t)warp * DD);
    op[lane] = o0; op[lane + 32] = o1;
}

// ============================================================================
// normalize codebook rows + exact tf32 split (permuted) + max ||bl||.
// ============================================================================
__global__ void norm_split_embed(const float* __restrict__ in) {
    int warp = (blockIdx.x * blockDim.x + threadIdx.x) >> 5;
    int lane = threadIdx.x & 31;
    if (warp >= NK) return;
    const float4* ip = reinterpret_cast<const float4*>(in + (size_t)warp * DD);
    float4 v0 = ip[lane];
    float4 v1 = ip[lane + 32];
    float s = v0.x*v0.x + v0.y*v0.y + v0.z*v0.z + v0.w*v0.w
            + v1.x*v1.x + v1.y*v1.y + v1.z*v1.z + v1.w*v1.w;
    #pragma unroll
    for (int off = 16; off > 0; off >>= 1) s += __shfl_xor_sync(0xFFFFFFFFu, s, off);
    float inv = 1.0f / fmaxf(sqrtf(s), 1e-12f);
    float vv[8] = {v0.x, v0.y, v0.z, v0.w, v1.x, v1.y, v1.z, v1.w};
    float bl2 = 0.0f;
    #pragma unroll
    for (int i = 0; i < 8; i++) {
        int c = (i < 4) ? (lane * 4 + i) : (128 + lane * 4 + (i - 4));
        float v = vv[i] * inv;
        float h = tf32_rna(v);
        float l = v - h;
        int dp = dperm(c);
        g_Bhi[(size_t)warp * DD + dp] = h;
        g_Blo[(size_t)warp * DD + dp] = l;
        bl2 += l * l;
    }
    #pragma unroll
    for (int off = 16; off > 0; off >>= 1) bl2 += __shfl_xor_sync(0xFFFFFFFFu, bl2, off);
    if (lane == 0) atomicMax(&g_maxBlBits, __float_as_int(sqrtf(bl2)));
}

// ============================================================================
// Transpose z -> token-major, exact tf32 split (permuted). Pure transform.
// ============================================================================
__global__ void transpose_split(const float* __restrict__ z) {
    __shared__ float t[32][33];
    int tx = threadIdx.x, ty = threadIdx.y;
    int hw0 = blockIdx.x * 32, d0 = blockIdx.y * 32, b = blockIdx.z;
    const float* zb = z + (size_t)b * DD * HWSZ;
    #pragma unroll
    for (int i = 0; i < 4; i++) {
        int d = d0 + ty + i * 8;
        t[ty + i * 8][tx] = zb[(size_t)d * HWSZ + hw0 + tx];
    }
    __syncthreads();
    int dp = d0 + dperm(tx);
    #pragma unroll
    for (int i = 0; i < 4; i++) {
        int hwl = ty + i * 8;
        int n = b * HWSZ + hw0 + hwl;
        float v = t[tx][hwl];
        float h = tf32_rna(v);
        float l = v - h;
        g_Ahi[(size_t)n * DD + dp] = h;
        g_Alo[(size_t)n * DD + dp] = l;
    }
}

// ============================================================================
// Per-token ||ah||^2 / ||al||^2: warp per token, coalesced float4 rows.
// ============================================================================
__global__ void norm_tokens() {
    int warp = (blockIdx.x * blockDim.x + threadIdx.x) >> 5;
    int lane = threadIdx.x & 31;
    if (warp >= NTOK) return;
    const float4* hp = reinterpret_cast<const float4*>(g_Ahi + (size_t)warp * DD);
    const float4* lp = reinterpret_cast<const float4*>(g_Alo + (size_t)warp * DD);
    float4 h0 = hp[lane], h1 = hp[lane + 32];
    float4 l0 = lp[lane], l1 = lp[lane + 32];
    float sh = h0.x*h0.x + h0.y*h0.y + h0.z*h0.z + h0.w*h0.w
             + h1.x*h1.x + h1.y*h1.y + h1.z*h1.z + h1.w*h1.w;
    float sl = l0.x*l0.x + l0.y*l0.y + l0.z*l0.z + l0.w*l0.w
             + l1.x*l1.x + l1.y*l1.y + l1.z*l1.z + l1.w*l1.w;
    #pragma unroll
    for (int off = 16; off > 0; off >>= 1) {
        sh += __shfl_xor_sync(0xFFFFFFFFu, sh, off);
        sl += __shfl_xor_sync(0xFFFFFFFFu, sl, off);
    }
    if (lane == 0) { g_nAh2[warp] = sh; g_nAl2[warp] = sl; }
}

// ============================================================================
// Coarse GEMM v8: 64 tok x 1024 codes, 128 thr, warptile 64x64 (nt=8):
// halves A-fragment crossbar bytes per mma (192 -> 128 B/mma), making the
// kernel tensor-bound instead of crossbar-bound. Stage = {A 64x16, B 256x16}
// @ stride-24 (30KB), 3-stage ring, 64 iters, 2 CTAs/SM.
// ============================================================================
#define CW3    24
#define ABUF3  6144            // A: 64*24*4
#define BBUF8  24576           // B: 256*24*4
#define STG8   (ABUF3+BBUF8)   // 30720
#define GSM8   (3*STG8)        // 92160

__global__ __launch_bounds__(128, 2) void coarse_gemm() {
    extern __shared__ float sm[];
    const uint32_t sbase = smem_to_u32(sm);
    const int tid  = threadIdx.x;
    const int wc   = tid >> 5;       // warp 0..3 -> 64-col band
    const int lane = tid & 31;
    const int g  = lane >> 2;
    const int tg = lane & 3;

    const int tile    = blockIdx.x >> 3;
    const int slice   = blockIdx.x & 7;
    const int rowBase = tile * 64;
    const int kBase   = slice * KSLICE;

    float acc[4][8][4];
    #pragma unroll
    for (int mt = 0; mt < 4; mt++)
        #pragma unroll
        for (int nt = 0; nt < 8; nt++)
            #pragma unroll
            for (int q = 0; q < 4; q++) acc[mt][nt][q] = 0.0f;

    float bestV[8], secV[8];
    int   bestI[8];
    #pragma unroll
    for (int s = 0; s < 8; s++) {
        bestV[s] = -INFINITY; secV[s] = -INFINITY; bestI[s] = 0x7fffffff;
    }

    // loader: A 2 chunks/thread, B 8 chunks/thread (256 rows)
    const int rA = tid >> 2;
    const int cA = tid & 3;
    const float* pA[2];
    const float* pB[8];
    uint32_t offA[2], offB[8];
    #pragma unroll
    for (int j = 0; j < 2; j++) {
        pA[j]   = g_Ahi + ((size_t)(rowBase + rA + 32 * j) * DD + cA * 4);
        offA[j] = (uint32_t)((rA + 32 * j) * 96 + cA * 16);
    }
    #pragma unroll
    for (int j = 0; j < 8; j++) {
        pB[j]   = g_Bhi + ((size_t)(kBase + rA + 32 * j) * DD + cA * 4);
        offB[j] = (uint32_t)(ABUF3 + (rA + 32 * j) * 96 + cA * 16);
    }
    int ldj = 0;
    auto load = [&](uint32_t sb) {
        cpasync16(sb + offA[0], pA[0]);
        cpasync16(sb + offA[1], pA[1]);
        #pragma unroll
        for (int j = 0; j < 8; j++) cpasync16(sb + offB[j], pB[j]);
        CPASYNC_COMMIT();
        int wrap = ((ldj & 15) == 15);
        ldj++;
        int dA = wrap ? (16 - 256) : 16;
        int dB = wrap ? (16 - 256 + 256 * DD) : 16;
        pA[0] += dA; pA[1] += dA;
        #pragma unroll
        for (int j = 0; j < 8; j++) pB[j] += dB;
    };

    const uint32_t stB0 = sbase, stB1 = sbase + STG8, stB2 = sbase + 2 * STG8;
    load(stB0); load(stB1);
    CPASYNC_WAIT(1);
    __syncthreads();

    int stg = 0;
    uint32_t stNext = stB2;
    for (int it = 0; it < 64; it++) {
        if (it < 62) load(stNext);

        const float* Ah = sm + stg * (STG8 / 4);
        const float* Bh = Ah + (ABUF3 / 4);

        #pragma unroll
        for (int ks = 0; ks < 2; ks++) {
            int kp = ks * 8 + 2 * tg;
            float2 af[4][2], bf[8];
            #pragma unroll
            for (int mt = 0; mt < 4; mt++) {
                const float* p = Ah + (mt * 16 + g) * CW3 + kp;
                af[mt][0] = *(const float2*)p;
                af[mt][1] = *(const float2*)(p + 8 * CW3);
            }
            #pragma unroll
            for (int nt = 0; nt < 8; nt++)
                bf[nt] = *(const float2*)(Bh + (wc * 64 + nt * 8 + g) * CW3 + kp);
            #pragma unroll
            for (int mt = 0; mt < 4; mt++)
                #pragma unroll
                for (int nt = 0; nt < 8; nt++) {
                    float a[4] = {af[mt][0].x, af[mt][1].x, af[mt][0].y, af[mt][1].y};
                    float b[2] = {bf[nt].x, bf[nt].y};
                    mma8(acc[mt][nt], a, b);
                }
        }

        if ((it & 15) == 15) {
            int colBase = kBase + (it >> 4) * 256 + wc * 64;
            #pragma unroll
            for (int mt = 0; mt < 4; mt++)
                #pragma unroll
                for (int half = 0; half < 2; half++) {
                    int slot = mt * 2 + half;
                    float v[16];
                    #pragma unroll
                    for (int nt = 0; nt < 8; nt++)
                        #pragma unroll
                        for (int j = 0; j < 2; j++)
                            v[nt * 2 + j] = acc[mt][nt][half * 2 + j];
                    float m[8];
                    #pragma unroll
                    for (int q = 0; q < 8; q++) m[q] = fmaxf(v[2*q], v[2*q+1]);
                    float m03 = fmaxf(fmaxf(m[0], m[1]), fmaxf(m[2], m[3]));
                    float m47 = fmaxf(fmaxf(m[4], m[5]), fmaxf(m[6], m[7]));
                    float m1  = fmaxf(m03, m47);
                    if (m1 > bestV[slot]) {
                        secV[slot] = fmaxf(secV[slot], bestV[slot]);
                        int bi = 0x7fffffff;
                        #pragma unroll
                        for (int q = 0; q < 16; q++)
                            if (v[q] == m1) bi = min(bi, colBase + (q >> 1) * 8 + tg * 2 + (q & 1));
                        float m2 = -INFINITY;
                        #pragma unroll
                        for (int q = 0; q < 16; q++) {
                            int cq = colBase + (q >> 1) * 8 + tg * 2 + (q & 1);
                            m2 = fmaxf(m2, (cq == bi) ? -INFINITY : v[q]);
                        }
                        bestV[slot] = m1;
                        bestI[slot] = bi;
                        secV[slot]  = fmaxf(secV[slot], m2);
                    } else {
                        secV[slot] = fmaxf(secV[slot], m1);
                    }
                }
            #pragma unroll
            for (int mt = 0; mt < 4; mt++)
                #pragma unroll
                for (int nt = 0; nt < 8; nt++)
                    #pragma unroll
                    for (int q = 0; q < 4; q++) acc[mt][nt][q] = 0.0f;
        }

        if (it < 62) CPASYNC_WAIT(1);
        else         CPASYNC_WAIT(0);
        __syncthreads();

        stg++; if (stg == 3) stg = 0;
        stNext += STG8; if (stNext > stB2) stNext = stB0;
    }

    // cross-thread merge: 16 contributors (wc x tg) per row, 64 rows
    float* sv1 = sm;
    int*   si1 = (int*)(sm + 1024);
    float* sv2 = sm + 2048;
    #pragma unroll
    for (int slot = 0; slot < 8; slot++) {
        int row = (slot >> 1) * 16 + (slot & 1) * 8 + g;
        int ent = row * 16 + wc * 4 + tg;
        sv1[ent] = bestV[slot];
        si1[ent] = bestI[slot];
        sv2[ent] = secV[slot];
    }
    __syncthreads();
    if (tid < 64) {
        float V1 = -INFINITY, V2 = -INFINITY;
        int I1 = 0x7fffffff;
        #pragma unroll
        for (int t = 0; t < 16; t++) {
            float v1 = sv1[tid * 16 + t];
            int   i1 = si1[tid * 16 + t];
            float v2 = sv2[tid * 16 + t];
            if (v1 > V1 || (v1 == V1 && i1 < I1)) {
                V2 = fmaxf(fmaxf(V2, V1), v2);
                V1 = v1; I1 = i1;
            } else {
                V2 = fmaxf(V2, v1);
            }
        }
        size_t e = (size_t)blockIdx.x * 64 + tid;
        g_pv[e] = make_float2(V1, V2);
        g_pi[e] = I1;
    }
}

// ============================================================================
// Merge slices + rigorous margin test; flag uncertain tokens.
// ============================================================================
__global__ void merge_kernel() {
    int n = blockIdx.x * blockDim.x + threadIdx.x;
    if (n >= NTOK) return;
    int tile = n >> 6, row = n & 63;
    float V1 = -INFINITY, V2 = -INFINITY;
    int I1 = 0x7fffffff;
    #pragma unroll
    for (int s = 0; s < NSLICE; s++) {
        size_t e = ((size_t)(tile * NSLICE + s)) * 64 + row;
        float2 v = g_pv[e];
        int   i1 = g_pi[e];
        if (v.x > V1 || (v.x == V1 && i1 < I1)) {
            V2 = fmaxf(fmaxf(V2, V1), v.y);
            V1 = v.x; I1 = i1;
        } else {
            V2 = fmaxf(V2, v.x);
        }
    }
    float maxBl = __int_as_float(g_maxBlBits);
    float nAh = sqrtf(g_nAh2[n]);
    float nAl = sqrtf(g_nAl2[n]);
    float margin = nAl * 1.0001f + nAh * (maxBl + 5e-5f);
    if (V1 - V2 >= 2.0f * margin) {
        g_idx[n] = I1;
    } else {
        int s = atomicAdd(&g_flagCnt, 1);
        g_flagTok[s] = n;
        g_idx[n] = I1;
    }
}

// ============================================================================
// 3xTF32 tensor-core rescore (R7-proven version).
// ============================================================================
#define RABUF  6144                 // Ah 64x24x4 (Al at +RABUF)
#define RBBUF  12288                // Bh 128x24x4
#define RBOFF  (2*RABUF)            // Bh base (Bl at +RBBUF)
#define RSTG   (2*RABUF + 2*RBBUF)  // 36864
#define RGSM   (2*RSTG)             // 73728

__global__ __launch_bounds__(128, 2) void rescore_mma() {
    extern __shared__ float sm[];
    const uint32_t sbase = smem_to_u32(sm);
    __shared__ int toks[64];
    int count = g_flagCnt;
    const int tile  = blockIdx.x >> 3;
    const int slice = blockIdx.x & 7;
    const int base  = tile * 64;
    if (base >= count) return;
    const int tid  = threadIdx.x;
    const int wc   = tid >> 5;
    const int lane = tid & 31;
    const int g  = lane >> 2;
    const int tg = lane & 3;
    const int kBase = slice * KSLICE;

    if (tid < 64) toks[tid] = (base + tid < count) ? g_flagTok[base + tid] : g_flagTok[0];
    __syncthreads();

    const ptrdiff_t ALO = g_Alo - g_Ahi;
    const ptrdiff_t BLO = g_Blo - g_Bhi;

    const int rA = tid >> 2;
    const int cA = tid & 3;
    const float* pA[2];
    const float* pB[4];
    uint32_t offA[2], offB[4];
    #pragma unroll
    for (int j = 0; j < 2; j++) {
        pA[j]   = g_Ahi + ((size_t)toks[rA + 32 * j] * DD + cA * 4);
        offA[j] = (uint32_t)((rA + 32 * j) * 96 + cA * 16);
    }
    #pragma unroll
    for (int j = 0; j < 4; j++) {
        pB[j]   = g_Bhi + ((size_t)(kBase + rA + 32 * j) * DD + cA * 4);
        offB[j] = (uint32_t)(RBOFF + (rA + 32 * j) * 96 + cA * 16);
    }
    int ldj = 0;
    auto load = [&](uint32_t sb) {
        #pragma unroll
        for (int j = 0; j < 2; j++) {
            cpasync16(sb + offA[j],         pA[j]);
            cpasync16(sb + offA[j] + RABUF, pA[j] + ALO);
        }
        #pragma unroll
        for (int j = 0; j < 4; j++) {
            cpasync16(sb + offB[j],         pB[j]);
            cpasync16(sb + offB[j] + RBBUF, pB[j] + BLO);
        }
        CPASYNC_COMMIT();
        int wrap = ((ldj & 15) == 15);
        ldj++;
        int dA = wrap ? (16 - 256) : 16;
        int dB = wrap ? (16 - 256 + 128 * DD) : 16;
        pA[0] += dA; pA[1] += dA;
        #pragma unroll
        for (int j = 0; j < 4; j++) pB[j] += dB;
    };

    float acc[4][4][4];
    #pragma unroll
    for (int mt = 0; mt < 4; mt++)
        #pragma unroll
        for (int nt = 0; nt < 4; nt++)
            #pragma unroll
            for (int q = 0; q < 4; q++) acc[mt][nt][q] = 0.0f;

    float bestV[8];
    int   bestI[8];
    #pragma unroll
    for (int s = 0; s < 8; s++) { bestV[s] = -INFINITY; bestI[s] = 0x7fffffff; }

    load(sbase);
    CPASYNC_WAIT(0);
    __syncthreads();

    for (int it = 0; it < 128; it++) {
        int stg = it & 1;
        if (it < 127) load(sbase + ((it + 1) & 1) * RSTG);

        const float* Ah = sm + stg * (RSTG / 4);
        const float* Al = Ah + (RABUF / 4);
        const float* Bh = Ah + (RBOFF / 4);
        const float* Bl = Bh + (RBBUF / 4);

        #pragma unroll
        for (int ks = 0; ks < 2; ks++) {
            int kp = ks * 8 + 2 * tg;
            float2 ah[4][2], al[4][2], bh[4], bl[4];
            #pragma unroll
            for (int mt = 0; mt < 4; mt++) {
                int ro = (mt * 16 + g) * CW3 + kp;
                ah[mt][0] = *(const float2*)(Ah + ro);
                ah[mt][1] = *(const float2*)(Ah + ro + 8 * CW3);
                al[mt][0] = *(const float2*)(Al + ro);
                al[mt][1] = *(const float2*)(Al + ro + 8 * CW3);
            }
            #pragma unroll
            for (int nt = 0; nt < 4; nt++) {
                int co = (wc * 32 + nt * 8 + g) * CW3 + kp;
                bh[nt] = *(const float2*)(Bh + co);
                bl[nt] = *(const float2*)(Bl + co);
            }
            #pragma unroll
            for (int mt = 0; mt < 4; mt++)
                #pragma unroll
                for (int nt = 0; nt < 4; nt++) {
                    float ahr[4] = {ah[mt][0].x, ah[mt][1].x, ah[mt][0].y, ah[mt][1].y};
                    float alr[4] = {al[mt][0].x, al[mt][1].x, al[mt][0].y, al[mt][1].y};
                    float bhr[2] = {bh[nt].x, bh[nt].y};
                    float blr[2] = {bl[nt].x, bl[nt].y};
                    mma8(acc[mt][nt], ahr, bhr);
                    mma8(acc[mt][nt], ahr, blr);
                    mma8(acc[mt][nt], alr, bhr);
                }
        }

        if ((it & 15) == 15) {
            int colBase = kBase + (it >> 4) * 128 + wc * 32;
            #pragma unroll
            for (int mt = 0; mt < 4; mt++)
                #pragma unroll
                for (int half = 0; half < 2; half++) {
                    int slot = mt * 2 + half;
                    float v[8];
                    #pragma unroll
                    for (int nt = 0; nt < 4; nt++)
                        #pragma unroll
                        for (int j = 0; j < 2; j++)
                            v[nt * 2 + j] = acc[mt][nt][half * 2 + j];
                    float m01 = fmaxf(v[0], v[1]), m23 = fmaxf(v[2], v[3]);
                    float m45 = fmaxf(v[4], v[5]), m67 = fmaxf(v[6], v[7]);
                    float m1  = fmaxf(fmaxf(m01, m23), fmaxf(m45, m67));
                    if (m1 > bestV[slot]) {
                        int bi = 0x7fffffff;
                        #pragma unroll
                        for (int q = 0; q < 8; q++)
                            if (v[q] == m1) bi = min(bi, colBase + (q >> 1) * 8 + tg * 2 + (q & 1));
                        bestV[slot] = m1;
                        bestI[slot] = bi;
                    }
                }
            #pragma unroll
            for (int mt = 0; mt < 4; mt++)
                #pragma unroll
                for (int nt = 0; nt < 4; nt++)
                    #pragma unroll
                    for (int q = 0; q < 4; q++) acc[mt][nt][q] = 0.0f;
        }

        CPASYNC_WAIT(0);
        __syncthreads();
    }

    // cross-thread merge: 16 contributors per row, 64 rows
    float* sv = sm;
    int*   si = (int*)(sm + 1024);
    #pragma unroll
    for (int slot = 0; slot < 8; slot++) {
        int row = (slot >> 1) * 16 + (slot & 1) * 8 + g;
        int ent = row * 16 + wc * 4 + tg;
        sv[ent] = bestV[slot];
        si[ent] = bestI[slot];
    }
    __syncthreads();
    if (tid < 64 && base + tid < count) {
        float bv = sv[tid * 16];
        int   bi = si[tid * 16];
        #pragma unroll
        for (int t = 1; t < 16; t++) {
            float v = sv[tid * 16 + t];
            int  id = si[tid * 16 + t];
            if (v > bv || (v == bv && id < bi)) { bv = v; bi = id; }
        }
        g_rv[(size_t)(base + tid) * 8 + slice] = bv;
        g_ri[(size_t)(base + tid) * 8 + slice] = bi;
    }
}

// ============================================================================
// merge2: fold 8 slice partials for flagged tokens
// ============================================================================
__global__ void merge2_kernel() {
    int slot = blockIdx.x * blockDim.x + threadIdx.x;
    if (slot >= g_flagCnt || slot >= NTOK) return;
    float bv = -INFINITY; int bi = 0x7fffffff;
    #pragma unroll
    for (int s = 0; s < 8; s++) {
        float v = g_rv[(size_t)slot * 8 + s];
        int   i = g_ri[(size_t)slot * 8 + s];
        if (v > bv || (v == bv && i < bi)) { bv = v; bi = i; }
    }
    g_idx[g_flagTok[slot]] = bi;
}

// ============================================================================
// finish: EMA scatter + outputs in one z pass
// ============================================================================
__global__ void finish_kernel(const float* __restrict__ z,
                              const float* __restrict__ embedding,
                              float* __restrict__ avg_out,
                              float* __restrict__ cs_out,
                              float* __restrict__ zst,
                              float* __restrict__ zq,
                              float* __restrict__ idxf) {
    int t = blockIdx.x * blockDim.x + threadIdx.x;
    if (t >= ZELEMS) return;
    int hw = t & (HWSZ - 1);
    int bd = t >> 12;
    int d  = bd & (DD - 1);
    int b  = bd >> 8;
    int n  = (b << 12) | hw;
    int id = __ldg(&g_idx[n]);
    float v = z[t];
    atomicAdd(&avg_out[id * DD + d], 0.01f * v);
    float e = __ldg(&embedding[id * DD + d]);
    zq[t]  = e;
    zst[t] = v + (e - v);
    if (d == 0) {
        atomicAdd(&cs_out[id], 0.01f);
        idxf[n] = (float)id;
    }
}

// ============================================================================
extern "C" void kernel_launch(void* const* d_in, const int* in_sizes, int n_in,
                              void* d_out, int out_size) {
    const float* z            = (const float*)d_in[0];
    const float* embedding    = (const float*)d_in[1];
    const float* cluster_size = (const float*)d_in[2];
    const float* embed_avg    = (const float*)d_in[3];

    float* out   = (float*)d_out;
    float* zst_o = out + OFF_ZST;
    float* idx_o = out + OFF_IDX;
    float* zq_o  = out + OFF_ZQ;
    float* emb_o = out + OFF_EMB;
    float* cs_o  = out + OFF_CS;
    float* avg_o = out + OFF_AVG;

    init_kernel<<<(NK * DD + 255) / 256, 256>>>(cluster_size, embed_avg, cs_o, avg_o);

    norm_split_embed<<<NK / 8, 256>>>(embedding);
    transpose_split<<<dim3(HWSZ / 32, DD / 32, 8), dim3(32, 8)>>>(z);
    norm_tokens<<<NTOK / 8, 256>>>();

    static bool attr_set = false;
    if (!attr_set) {
        cudaFuncSetAttribute(coarse_gemm,
                             cudaFuncAttributeMaxDynamicSharedMemorySize, GSM8);
        cudaFuncSetAttribute(rescore_mma,
                             cudaFuncAttributeMaxDynamicSharedMemorySize, RGSM);
        attr_set = true;
    }
    coarse_gemm<<<NTILE64 * NSLICE, 128, GSM8>>>();

    merge_kernel<<<NTOK / 256, 256>>>();

    rescore_mma<<<(NTOK / 64) * 8, 128, RGSM>>>();

    merge2_kernel<<<NTOK / 256, 256>>>();

    finish_kernel<<<ZELEMS / 256, 256>>>(z, embedding, avg_o, cs_o, zst_o, zq_o, idx_o);

    norm_rows_kernel<<<NK / 8, 256>>>(avg_o, emb_o, NK);
}

// round 13
// speedup vs baseline: 1.0050x; 1.0050x over previous
#include <cuda_runtime.h>
#include <cuda_bf16.h>
#include <math.h>
#include <stdint.h>

// Problem constants
#define NK    8192
#define DD    256
#define NTOK  32768
#define HWSZ  4096
#define ZELEMS 8388608

// Output layout offsets (float32, reference return order)
#define OFF_ZST  0
#define OFF_IDX  8388608
#define OFF_ZQ   8421376
#define OFF_EMB  16809984
#define OFF_CS   18907136
#define OFF_AVG  18915328

#define NSLICE 8
#define KSLICE 1024
#define NTILE  256        // NTOK / 128  (coarse: 128-token tiles)

// Scratch (__device__ globals)
__device__ float g_Ahi[NTOK * DD];
__device__ float g_Alo[NTOK * DD];
__device__ float g_Bhi[NK * DD];
__device__ float g_Blo[NK * DD];
__device__ float g_nAh2[NTOK];
__device__ float g_nAl2[NTOK];
__device__ int   g_maxBlBits;
__device__ float2 g_pv[NTILE * NSLICE * 128];   // (V1, V2)
__device__ int    g_pi[NTILE * NSLICE * 128];   // I1
__device__ int   g_flagCnt;
__device__ int   g_flagTok[NTOK];
__device__ float g_rv[NTOK * 8];
__device__ int   g_ri[NTOK * 8];
__device__ int   g_idx[NTOK];

// ============================================================================
// helpers
// ============================================================================
__device__ __forceinline__ uint32_t smem_to_u32(const void* p) {
    uint32_t a;
    asm("{ .reg .u64 t; cvta.to.shared.u64 t, %1; cvt.u32.u64 %0, t; }" : "=r"(a) : "l"(p));
    return a;
}
__device__ __forceinline__ void cpasync16(uint32_t dst, const void* src) {
    asm volatile("cp.async.cg.shared.global [%0], [%1], 16;" :: "r"(dst), "l"(src));
}
#define CPASYNC_COMMIT() asm volatile("cp.async.commit_group;" ::: "memory")
#define CPASYNC_WAIT(n)  asm volatile("cp.async.wait_group %0;" :: "n"(n) : "memory")

__device__ __forceinline__ float tf32_rna(float x) {
    uint32_t u;
    asm("cvt.rna.tf32.f32 %0, %1;" : "=r"(u) : "f"(x));
    return __uint_as_float(u);
}

__device__ __forceinline__ void mma8(float* c, const float* a, const float* b) {
    asm volatile(
        "mma.sync.aligned.m16n8k8.row.col.f32.tf32.tf32.f32 "
        "{%0,%1,%2,%3}, {%4,%5,%6,%7}, {%8,%9}, {%0,%1,%2,%3};"
        : "+f"(c[0]), "+f"(c[1]), "+f"(c[2]), "+f"(c[3])
        : "r"(__float_as_uint(a[0])), "r"(__float_as_uint(a[1])),
          "r"(__float_as_uint(a[2])), "r"(__float_as_uint(a[3])),
          "r"(__float_as_uint(b[0])), "r"(__float_as_uint(b[1])));
}

// permuted column position within 8-groups: p=(c&3)*2+(c>>2)
__device__ __forceinline__ int dperm(int c) {
    int inner = c & 7;
    return (c & ~7) + ((inner & 3) * 2) + (inner >> 2);
}

// ============================================================================
// init
// ============================================================================
__global__ void init_kernel(const float* __restrict__ cluster_size,
                            const float* __restrict__ embed_avg,
                            float* __restrict__ cs_out,
                            float* __restrict__ avg_out) {
    int t = blockIdx.x * blockDim.x + threadIdx.x;
    if (t < NK) cs_out[t] = 0.99f * cluster_size[t];
    if (t < NK * DD) avg_out[t] = 0.99f * embed_avg[t];
    if (t == 0) { g_maxBlBits = 0; g_flagCnt = 0; }
}

// ============================================================================
// Row L2-normalize (final new_embedding). One warp per row.
// ============================================================================
__global__ void norm_rows_kernel(const float* __restrict__ in,
                                 float* __restrict__ out, int nrows) {
    int warp = (blockIdx.x * blockDim.x + threadIdx.x) >> 5;
    int lane = threadIdx.x & 31;
    if (warp >= nrows) return;
    const float4* ip = reinterpret_cast<const float4*>(in + (size_t)warp * DD);
    float4 v0 = ip[lane];
    float4 v1 = ip[lane + 32];
    float s = v0.x*v0.x + v0.y*v0.y + v0.z*v0.z + v0.w*v0.w
            + v1.x*v1.x + v1.y*v1.y + v1.z*v1.z + v1.w*v1.w;
    #pragma unroll
    for (int off = 16; off > 0; off >>= 1) s += __shfl_xor_sync(0xFFFFFFFFu, s, off);
    float nrm = fmaxf(sqrtf(s), 1e-12f);
    float4 o0, o1;
    o0.x = v0.x/nrm; o0.y = v0.y/nrm; o0.z = v0.z/nrm; o0.w = v0.w/nrm;
    o1.x = v1.x/nrm; o1.y = v1.y/nrm; o1.z = v1.z/nrm; o1.w = v1.w/nrm;
    float4* op = reinterpret_cast<float4*>(out + (size_t)warp * DD);
    op[lane] = o0; op[lane + 32] = o1;
}

// ============================================================================
// normalize codebook rows + exact tf32 split (permuted) + max ||bl||.
// ============================================================================
__global__ void norm_split_embed(const float* __restrict__ in) {
    int warp = (blockIdx.x * blockDim.x + threadIdx.x) >> 5;
    int lane = threadIdx.x & 31;
    if (warp >= NK) return;
    const float4* ip = reinterpret_cast<const float4*>(in + (size_t)warp * DD);
    float4 v0 = ip[lane];
    float4 v1 = ip[lane + 32];
    float s = v0.x*v0.x + v0.y*v0.y + v0.z*v0.z + v0.w*v0.w
            + v1.x*v1.x + v1.y*v1.y + v1.z*v1.z + v1.w*v1.w;
    #pragma unroll
    for (int off = 16; off > 0; off >>= 1) s += __shfl_xor_sync(0xFFFFFFFFu, s, off);
    float inv = 1.0f / fmaxf(sqrtf(s), 1e-12f);
    float vv[8] = {v0.x, v0.y, v0.z, v0.w, v1.x, v1.y, v1.z, v1.w};
    float bl2 = 0.0f;
    #pragma unroll
    for (int i = 0; i < 8; i++) {
        int c = (i < 4) ? (lane * 4 + i) : (128 + lane * 4 + (i - 4));
        float v = vv[i] * inv;
        float h = tf32_rna(v);
        float l = v - h;
        int dp = dperm(c);
        g_Bhi[(size_t)warp * DD + dp] = h;
        g_Blo[(size_t)warp * DD + dp] = l;
        bl2 += l * l;
    }
    #pragma unroll
    for (int off = 16; off > 0; off >>= 1) bl2 += __shfl_xor_sync(0xFFFFFFFFu, bl2, off);
    if (lane == 0) atomicMax(&g_maxBlBits, __float_as_int(sqrtf(bl2)));
}

// ============================================================================
// Transpose z -> token-major, exact tf32 split (permuted). Pure transform.
// ============================================================================
__global__ void transpose_split(const float* __restrict__ z) {
    __shared__ float t[32][33];
    int tx = threadIdx.x, ty = threadIdx.y;
    int hw0 = blockIdx.x * 32, d0 = blockIdx.y * 32, b = blockIdx.z;
    const float* zb = z + (size_t)b * DD * HWSZ;
    #pragma unroll
    for (int i = 0; i < 4; i++) {
        int d = d0 + ty + i * 8;
        t[ty + i * 8][tx] = zb[(size_t)d * HWSZ + hw0 + tx];
    }
    __syncthreads();
    int dp = d0 + dperm(tx);
    #pragma unroll
    for (int i = 0; i < 4; i++) {
        int hwl = ty + i * 8;
        int n = b * HWSZ + hw0 + hwl;
        float v = t[tx][hwl];
        float h = tf32_rna(v);
        float l = v - h;
        g_Ahi[(size_t)n * DD + dp] = h;
        g_Alo[(size_t)n * DD + dp] = l;
    }
}

// ============================================================================
// Per-token ||ah||^2 / ||al||^2: warp per token, coalesced float4 rows.
// ============================================================================
__global__ void norm_tokens() {
    int warp = (blockIdx.x * blockDim.x + threadIdx.x) >> 5;
    int lane = threadIdx.x & 31;
    if (warp >= NTOK) return;
    const float4* hp = reinterpret_cast<const float4*>(g_Ahi + (size_t)warp * DD);
    const float4* lp = reinterpret_cast<const float4*>(g_Alo + (size_t)warp * DD);
    float4 h0 = hp[lane], h1 = hp[lane + 32];
    float4 l0 = lp[lane], l1 = lp[lane + 32];
    float sh = h0.x*h0.x + h0.y*h0.y + h0.z*h0.z + h0.w*h0.w
             + h1.x*h1.x + h1.y*h1.y + h1.z*h1.z + h1.w*h1.w;
    float sl = l0.x*l0.x + l0.y*l0.y + l0.z*l0.z + l0.w*l0.w
             + l1.x*l1.x + l1.y*l1.y + l1.z*l1.z + l1.w*l1.w;
    #pragma unroll
    for (int off = 16; off > 0; off >>= 1) {
        sh += __shfl_xor_sync(0xFFFFFFFFu, sh, off);
        sl += __shfl_xor_sync(0xFFFFFFFFu, sl, off);
    }
    if (lane == 0) { g_nAh2[warp] = sh; g_nAl2[warp] = sl; }
}

// ============================================================================
// Coarse GEMM (R5-proven, 832us measured): CTA = 128 tokens x 1024 codes,
// 256 threads, 8 warps (2x4), warptile 64x32, d-chunk 32, 2 CTAs/SM,
// 2-stage cp.async, padded stride 40.
// ============================================================================
#define CW    40
#define ABUF  20480            // 128*40*4
#define STG   (2*ABUF)         // 40960 : Ah + Bh
#define GSM   (2*STG)          // 81920 : double buffer

__global__ __launch_bounds__(256, 2) void coarse_gemm() {
    extern __shared__ float sm[];
    const uint32_t sbase = smem_to_u32(sm);
    const int tid  = threadIdx.x;
    const int warp = tid >> 5;
    const int lane = tid & 31;
    const int wr = warp >> 2;        // 0..1  (64-row band)
    const int wc = warp & 3;         // 0..3  (32-col band)
    const int g  = lane >> 2;        // 0..7
    const int tg = lane & 3;         // 0..3

    const int tile    = blockIdx.x >> 3;
    const int slice   = blockIdx.x & 7;
    const int rowBase = tile * 128;
    const int kBase   = slice * KSLICE;

    float acc[4][4][4];
    #pragma unroll
    for (int mt = 0; mt < 4; mt++)
        #pragma unroll
        for (int nt = 0; nt < 4; nt++)
            #pragma unroll
            for (int q = 0; q < 4; q++) acc[mt][nt][q] = 0.0f;

    float bestV[8], secV[8];
    int   bestI[8];
    #pragma unroll
    for (int s = 0; s < 8; s++) {
        bestV[s] = -INFINITY; secV[s] = -INFINITY; bestI[s] = 0x7fffffff;
    }

    auto load_stage = [&](int it) {
        int stage = it & 1;
        int k0 = kBase + (it >> 3) * 128;
        int d0 = (it & 7) * 32;
        uint32_t sb = sbase + stage * STG;
        #pragma unroll
        for (int i = 0; i < 8; i++) {
            int ch = tid + i * 256;          // 0..2047
            uint32_t dst; const float* src;
            if (ch < 1024) {
                int r = ch >> 3, c = ch & 7;
                dst = sb + (uint32_t)(r * 160 + c * 16);
                src = g_Ahi + ((size_t)(rowBase + r) * DD + d0 + c * 4);
            } else {
                int c2 = ch - 1024;
                int r = c2 >> 3, c = c2 & 7;
                dst = sb + ABUF + (uint32_t)(r * 160 + c * 16);
                src = g_Bhi + ((size_t)(k0 + r) * DD + d0 + c * 4);
            }
            cpasync16(dst, src);
        }
        CPASYNC_COMMIT();
    };

    load_stage(0);

    for (int it = 0; it < 64; it++) {
        if (it + 1 < 64) { load_stage(it + 1); CPASYNC_WAIT(1); }
        else             { CPASYNC_WAIT(0); }
        __syncthreads();

        int stage = it & 1;
        const float* Ah = sm + stage * (STG / 4);
        const float* Bh = Ah + (ABUF / 4);

        #pragma unroll
        for (int ks = 0; ks < 4; ks++) {
            int kp = ks * 8 + 2 * tg;
            float2 af[4][2], bf[4];
            #pragma unroll
            for (int mt = 0; mt < 4; mt++) {
                const float* p = Ah + (wr * 64 + mt * 16 + g) * CW + kp;
                af[mt][0] = *(const float2*)p;
                af[mt][1] = *(const float2*)(p + 8 * CW);
            }
            #pragma unroll
            for (int nt = 0; nt < 4; nt++)
                bf[nt] = *(const float2*)(Bh + (wc * 32 + nt * 8 + g) * CW + kp);
            #pragma unroll
            for (int mt = 0; mt < 4; mt++)
                #pragma unroll
                for (int nt = 0; nt < 4; nt++) {
                    float a[4] = {af[mt][0].x, af[mt][1].x, af[mt][0].y, af[mt][1].y};
                    float b[2] = {bf[nt].x, bf[nt].y};
                    mma8(acc[mt][nt], a, b);
                }
        }

        if ((it & 7) == 7) {
            int colBase = kBase + (it >> 3) * 128 + wc * 32;
            #pragma unroll
            for (int mt = 0; mt < 4; mt++)
                #pragma unroll
                for (int half = 0; half < 2; half++) {
                    int slot = mt * 2 + half;
                    float v[8];
                    #pragma unroll
                    for (int nt = 0; nt < 4; nt++)
                        #pragma unroll
                        for (int j = 0; j < 2; j++)
                            v[nt * 2 + j] = acc[mt][nt][half * 2 + j];
                    float m01 = fmaxf(v[0], v[1]), m23 = fmaxf(v[2], v[3]);
                    float m45 = fmaxf(v[4], v[5]), m67 = fmaxf(v[6], v[7]);
                    float m1  = fmaxf(fmaxf(m01, m23), fmaxf(m45, m67));
                    if (m1 > bestV[slot]) {
                        secV[slot] = fmaxf(secV[slot], bestV[slot]);
                        int bi = 0x7fffffff;
                        #pragma unroll
                        for (int q = 0; q < 8; q++)
                            if (v[q] == m1) bi = min(bi, colBase + (q >> 1) * 8 + tg * 2 + (q & 1));
                        float m2 = -INFINITY;
                        #pragma unroll
                        for (int q = 0; q < 8; q++) {
                            int cq = colBase + (q >> 1) * 8 + tg * 2 + (q & 1);
                            m2 = fmaxf(m2, (cq == bi) ? -INFINITY : v[q]);
                        }
                        bestV[slot] = m1;
                        bestI[slot] = bi;
                        secV[slot]  = fmaxf(secV[slot], m2);
                    } else {
                        secV[slot] = fmaxf(secV[slot], m1);
                    }
                }
            #pragma unroll
            for (int mt = 0; mt < 4; mt++)
                #pragma unroll
                for (int nt = 0; nt < 4; nt++)
                    #pragma unroll
                    for (int q = 0; q < 4; q++) acc[mt][nt][q] = 0.0f;
        }
        __syncthreads();
    }

    // cross-thread merge: 16 contributors (wc x tg) per row, 128 rows
    float* sv1 = sm;                   // 2048 floats
    int*   si1 = (int*)(sm + 2048);
    float* sv2 = sm + 4096;
    #pragma unroll
    for (int slot = 0; slot < 8; slot++) {
        int row = wr * 64 + (slot >> 1) * 16 + (slot & 1) * 8 + g;
        int ent = row * 16 + wc * 4 + tg;
        sv1[ent] = bestV[slot];
        si1[ent] = bestI[slot];
        sv2[ent] = secV[slot];
    }
    __syncthreads();
    if (tid < 128) {
        float V1 = -INFINITY, V2 = -INFINITY;
        int I1 = 0x7fffffff;
        #pragma unroll
        for (int t = 0; t < 16; t++) {
            float v1 = sv1[tid * 16 + t];
            int   i1 = si1[tid * 16 + t];
            float v2 = sv2[tid * 16 + t];
            if (v1 > V1 || (v1 == V1 && i1 < I1)) {
                V2 = fmaxf(fmaxf(V2, V1), v2);
                V1 = v1; I1 = i1;
            } else {
                V2 = fmaxf(V2, v1);
            }
        }
        size_t e = (size_t)blockIdx.x * 128 + tid;
        g_pv[e] = make_float2(V1, V2);
        g_pi[e] = I1;
    }
}

// ============================================================================
// Merge slices + rigorous margin test; flag uncertain tokens. (128-row tiles)
// ============================================================================
__global__ void merge_kernel() {
    int n = blockIdx.x * blockDim.x + threadIdx.x;
    if (n >= NTOK) return;
    int tile = n >> 7, row = n & 127;
    float V1 = -INFINITY, V2 = -INFINITY;
    int I1 = 0x7fffffff;
    #pragma unroll
    for (int s = 0; s < NSLICE; s++) {
        size_t e = ((size_t)(tile * NSLICE + s)) * 128 + row;
        float2 v = g_pv[e];
        int   i1 = g_pi[e];
        if (v.x > V1 || (v.x == V1 && i1 < I1)) {
            V2 = fmaxf(fmaxf(V2, V1), v.y);
            V1 = v.x; I1 = i1;
        } else {
            V2 = fmaxf(V2, v.x);
        }
    }
    float maxBl = __int_as_float(g_maxBlBits);
    float nAh = sqrtf(g_nAh2[n]);
    float nAl = sqrtf(g_nAl2[n]);
    float margin = nAl * 1.0001f + nAh * (maxBl + 5e-5f);
    if (V1 - V2 >= 2.0f * margin) {
        g_idx[n] = I1;
    } else {
        int s = atomicAdd(&g_flagCnt, 1);
        g_flagTok[s] = n;
        g_idx[n] = I1;
    }
}

// ============================================================================
// 3xTF32 tensor-core rescore (R7-proven version).
// ============================================================================
#define CW3    24
#define RABUF  6144                 // Ah 64x24x4 (Al at +RABUF)
#define RBBUF  12288                // Bh 128x24x4
#define RBOFF  (2*RABUF)            // Bh base (Bl at +RBBUF)
#define RSTG   (2*RABUF + 2*RBBUF)  // 36864
#define RGSM   (2*RSTG)             // 73728

__global__ __launch_bounds__(128, 2) void rescore_mma() {
    extern __shared__ float sm[];
    const uint32_t sbase = smem_to_u32(sm);
    __shared__ int toks[64];
    int count = g_flagCnt;
    const int tile  = blockIdx.x >> 3;
    const int slice = blockIdx.x & 7;
    const int base  = tile * 64;
    if (base >= count) return;
    const int tid  = threadIdx.x;
    const int wc   = tid >> 5;
    const int lane = tid & 31;
    const int g  = lane >> 2;
    const int tg = lane & 3;
    const int kBase = slice * KSLICE;

    if (tid < 64) toks[tid] = (base + tid < count) ? g_flagTok[base + tid] : g_flagTok[0];
    __syncthreads();

    const ptrdiff_t ALO = g_Alo - g_Ahi;
    const ptrdiff_t BLO = g_Blo - g_Bhi;

    const int rA = tid >> 2;
    const int cA = tid & 3;
    const float* pA[2];
    const float* pB[4];
    uint32_t offA[2], offB[4];
    #pragma unroll
    for (int j = 0; j < 2; j++) {
        pA[j]   = g_Ahi + ((size_t)toks[rA + 32 * j] * DD + cA * 4);
        offA[j] = (uint32_t)((rA + 32 * j) * 96 + cA * 16);
    }
    #pragma unroll
    for (int j = 0; j < 4; j++) {
        pB[j]   = g_Bhi + ((size_t)(kBase + rA + 32 * j) * DD + cA * 4);
        offB[j] = (uint32_t)(RBOFF + (rA + 32 * j) * 96 + cA * 16);
    }
    int ldj = 0;
    auto load = [&](uint32_t sb) {
        #pragma unroll
        for (int j = 0; j < 2; j++) {
            cpasync16(sb + offA[j],         pA[j]);
            cpasync16(sb + offA[j] + RABUF, pA[j] + ALO);
        }
        #pragma unroll
        for (int j = 0; j < 4; j++) {
            cpasync16(sb + offB[j],         pB[j]);
            cpasync16(sb + offB[j] + RBBUF, pB[j] + BLO);
        }
        CPASYNC_COMMIT();
        int wrap = ((ldj & 15) == 15);
        ldj++;
        int dA = wrap ? (16 - 256) : 16;
        int dB = wrap ? (16 - 256 + 128 * DD) : 16;
        pA[0] += dA; pA[1] += dA;
        #pragma unroll
        for (int j = 0; j < 4; j++) pB[j] += dB;
    };

    float acc[4][4][4];
    #pragma unroll
    for (int mt = 0; mt < 4; mt++)
        #pragma unroll
        for (int nt = 0; nt < 4; nt++)
            #pragma unroll
            for (int q = 0; q < 4; q++) acc[mt][nt][q] = 0.0f;

    float bestV[8];
    int   bestI[8];
    #pragma unroll
    for (int s = 0; s < 8; s++) { bestV[s] = -INFINITY; bestI[s] = 0x7fffffff; }

    load(sbase);
    CPASYNC_WAIT(0);
    __syncthreads();

    for (int it = 0; it < 128; it++) {
        int stg = it & 1;
        if (it < 127) load(sbase + ((it + 1) & 1) * RSTG);

        const float* Ah = sm + stg * (RSTG / 4);
        const float* Al = Ah + (RABUF / 4);
        const float* Bh = Ah + (RBOFF / 4);
        const float* Bl = Bh + (RBBUF / 4);

        #pragma unroll
        for (int ks = 0; ks < 2; ks++) {
            int kp = ks * 8 + 2 * tg;
            float2 ah[4][2], al[4][2], bh[4], bl[4];
            #pragma unroll
            for (int mt = 0; mt < 4; mt++) {
                int ro = (mt * 16 + g) * CW3 + kp;
                ah[mt][0] = *(const float2*)(Ah + ro);
                ah[mt][1] = *(const float2*)(Ah + ro + 8 * CW3);
                al[mt][0] = *(const float2*)(Al + ro);
                al[mt][1] = *(const float2*)(Al + ro + 8 * CW3);
            }
            #pragma unroll
            for (int nt = 0; nt < 4; nt++) {
                int co = (wc * 32 + nt * 8 + g) * CW3 + kp;
                bh[nt] = *(const float2*)(Bh + co);
                bl[nt] = *(const float2*)(Bl + co);
            }
            #pragma unroll
            for (int mt = 0; mt < 4; mt++)
                #pragma unroll
                for (int nt = 0; nt < 4; nt++) {
                    float ahr[4] = {ah[mt][0].x, ah[mt][1].x, ah[mt][0].y, ah[mt][1].y};
                    float alr[4] = {al[mt][0].x, al[mt][1].x, al[mt][0].y, al[mt][1].y};
                    float bhr[2] = {bh[nt].x, bh[nt].y};
                    float blr[2] = {bl[nt].x, bl[nt].y};
                    mma8(acc[mt][nt], ahr, bhr);
                    mma8(acc[mt][nt], ahr, blr);
                    mma8(acc[mt][nt], alr, bhr);
                }
        }

        if ((it & 15) == 15) {
            int colBase = kBase + (it >> 4) * 128 + wc * 32;
            #pragma unroll
            for (int mt = 0; mt < 4; mt++)
                #pragma unroll
                for (int half = 0; half < 2; half++) {
                    int slot = mt * 2 + half;
                    float v[8];
                    #pragma unroll
                    for (int nt = 0; nt < 4; nt++)
                        #pragma unroll
                        for (int j = 0; j < 2; j++)
                            v[nt * 2 + j] = acc[mt][nt][half * 2 + j];
                    float m01 = fmaxf(v[0], v[1]), m23 = fmaxf(v[2], v[3]);
                    float m45 = fmaxf(v[4], v[5]), m67 = fmaxf(v[6], v[7]);
                    float m1  = fmaxf(fmaxf(m01, m23), fmaxf(m45, m67));
                    if (m1 > bestV[slot]) {
                        int bi = 0x7fffffff;
                        #pragma unroll
                        for (int q = 0; q < 8; q++)
                            if (v[q] == m1) bi = min(bi, colBase + (q >> 1) * 8 + tg * 2 + (q & 1));
                        bestV[slot] = m1;
                        bestI[slot] = bi;
                    }
                }
            #pragma unroll
            for (int mt = 0; mt < 4; mt++)
                #pragma unroll
                for (int nt = 0; nt < 4; nt++)
                    #pragma unroll
                    for (int q = 0; q < 4; q++) acc[mt][nt][q] = 0.0f;
        }

        CPASYNC_WAIT(0);
        __syncthreads();
    }

    // cross-thread merge: 16 contributors per row, 64 rows
    float* sv = sm;
    int*   si = (int*)(sm + 1024);
    #pragma unroll
    for (int slot = 0; slot < 8; slot++) {
        int row = (slot >> 1) * 16 + (slot & 1) * 8 + g;
        int ent = row * 16 + wc * 4 + tg;
        sv[ent] = bestV[slot];
        si[ent] = bestI[slot];
    }
    __syncthreads();
    if (tid < 64 && base + tid < count) {
        float bv = sv[tid * 16];
        int   bi = si[tid * 16];
        #pragma unroll
        for (int t = 1; t < 16; t++) {
            float v = sv[tid * 16 + t];
            int  id = si[tid * 16 + t];
            if (v > bv || (v == bv && id < bi)) { bv = v; bi = id; }
        }
        g_rv[(size_t)(base + tid) * 8 + slice] = bv;
        g_ri[(size_t)(base + tid) * 8 + slice] = bi;
    }
}

// ============================================================================
// merge2: fold 8 slice partials for flagged tokens
// ============================================================================
__global__ void merge2_kernel() {
    int slot = blockIdx.x * blockDim.x + threadIdx.x;
    if (slot >= g_flagCnt || slot >= NTOK) return;
    float bv = -INFINITY; int bi = 0x7fffffff;
    #pragma unroll
    for (int s = 0; s < 8; s++) {
        float v = g_rv[(size_t)slot * 8 + s];
        int   i = g_ri[(size_t)slot * 8 + s];
        if (v > bv || (v == bv && i < bi)) { bv = v; bi = i; }
    }
    g_idx[g_flagTok[slot]] = bi;
}

// ============================================================================
// finish: EMA scatter + outputs in one z pass
// ============================================================================
__global__ void finish_kernel(const float* __restrict__ z,
                              const float* __restrict__ embedding,
                              float* __restrict__ avg_out,
                              float* __restrict__ cs_out,
                              float* __restrict__ zst,
                              float* __restrict__ zq,
                              float* __restrict__ idxf) {
    int t = blockIdx.x * blockDim.x + threadIdx.x;
    if (t >= ZELEMS) return;
    int hw = t & (HWSZ - 1);
    int bd = t >> 12;
    int d  = bd & (DD - 1);
    int b  = bd >> 8;
    int n  = (b << 12) | hw;
    int id = __ldg(&g_idx[n]);
    float v = z[t];
    atomicAdd(&avg_out[id * DD + d], 0.01f * v);
    float e = __ldg(&embedding[id * DD + d]);
    zq[t]  = e;
    zst[t] = v + (e - v);
    if (d == 0) {
        atomicAdd(&cs_out[id], 0.01f);
        idxf[n] = (float)id;
    }
}

// ============================================================================
extern "C" void kernel_launch(void* const* d_in, const int* in_sizes, int n_in,
                              void* d_out, int out_size) {
    const float* z            = (const float*)d_in[0];
    const float* embedding    = (const float*)d_in[1];
    const float* cluster_size = (const float*)d_in[2];
    const float* embed_avg    = (const float*)d_in[3];

    float* out   = (float*)d_out;
    float* zst_o = out + OFF_ZST;
    float* idx_o = out + OFF_IDX;
    float* zq_o  = out + OFF_ZQ;
    float* emb_o = out + OFF_EMB;
    float* cs_o  = out + OFF_CS;
    float* avg_o = out + OFF_AVG;

    init_kernel<<<(NK * DD + 255) / 256, 256>>>(cluster_size, embed_avg, cs_o, avg_o);

    norm_split_embed<<<NK / 8, 256>>>(embedding);
    transpose_split<<<dim3(HWSZ / 32, DD / 32, 8), dim3(32, 8)>>>(z);
    norm_tokens<<<NTOK / 8, 256>>>();

    static bool attr_set = false;
    if (!attr_set) {
        cudaFuncSetAttribute(coarse_gemm,
                             cudaFuncAttributeMaxDynamicSharedMemorySize, GSM);
        cudaFuncSetAttribute(rescore_mma,
                             cudaFuncAttributeMaxDynamicSharedMemorySize, RGSM);
        attr_set = true;
    }
    coarse_gemm<<<NTILE * NSLICE, 256, GSM>>>();

    merge_kernel<<<NTOK / 256, 256>>>();

    rescore_mma<<<(NTOK / 64) * 8, 128, RGSM>>>();

    merge2_kernel<<<NTOK / 256, 256>>>();

    finish_kernel<<<ZELEMS / 256, 256>>>(z, embedding, avg_o, cs_o, zst_o, zq_o, idx_o);

    norm_rows_kernel<<<NK / 8, 256>>>(avg_o, emb_o, NK);
}

// round 14
// speedup vs baseline: 1.0357x; 1.0306x over previous
#include <cuda_runtime.h>
#include <cuda_bf16.h>
#include <math.h>
#include <stdint.h>

// Problem constants
#define NK    8192
#define DD    256
#define NTOK  32768
#define HWSZ  4096
#define ZELEMS 8388608

// Output layout offsets (float32, reference return order)
#define OFF_ZST  0
#define OFF_IDX  8388608
#define OFF_ZQ   8421376
#define OFF_EMB  16809984
#define OFF_CS   18907136
#define OFF_AVG  18915328

#define NSLICE 8
#define KSLICE 1024
#define NTILE64 512       // NTOK / 64

// Scratch (__device__ globals)
__device__ float g_Ahi[NTOK * DD];
__device__ float g_Alo[NTOK * DD];
__device__ float g_Bhi[NK * DD];
__device__ float g_Blo[NK * DD];
__device__ float g_nAh2[NTOK];
__device__ float g_nAl2[NTOK];
__device__ int   g_maxBlBits;
__device__ float2 g_pv[NTILE64 * NSLICE * 64];   // (V1, V2)
__device__ int    g_pi[NTILE64 * NSLICE * 64];   // I1
__device__ int   g_flagCnt;
__device__ int   g_flagTok[NTOK];
__device__ float g_rv[NTOK * 8];
__device__ int   g_ri[NTOK * 8];
__device__ int   g_idx[NTOK];
__device__ float g_zqT[NTOK * DD];   // token-major staging (logical column order)
__device__ float g_zstT[NTOK * DD];

// ============================================================================
// helpers
// ============================================================================
__device__ __forceinline__ uint32_t smem_to_u32(const void* p) {
    uint32_t a;
    asm("{ .reg .u64 t; cvta.to.shared.u64 t, %1; cvt.u32.u64 %0, t; }" : "=r"(a) : "l"(p));
    return a;
}
__device__ __forceinline__ void cpasync16(uint32_t dst, const void* src) {
    asm volatile("cp.async.cg.shared.global [%0], [%1], 16;" :: "r"(dst), "l"(src));
}
#define CPASYNC_COMMIT() asm volatile("cp.async.commit_group;" ::: "memory")
#define CPASYNC_WAIT(n)  asm volatile("cp.async.wait_group %0;" :: "n"(n) : "memory")

__device__ __forceinline__ float tf32_rna(float x) {
    uint32_t u;
    asm("cvt.rna.tf32.f32 %0, %1;" : "=r"(u) : "f"(x));
    return __uint_as_float(u);
}

__device__ __forceinline__ void mma8(float* c, const float* a, const float* b) {
    asm volatile(
        "mma.sync.aligned.m16n8k8.row.col.f32.tf32.tf32.f32 "
        "{%0,%1,%2,%3}, {%4,%5,%6,%7}, {%8,%9}, {%0,%1,%2,%3};"
        : "+f"(c[0]), "+f"(c[1]), "+f"(c[2]), "+f"(c[3])
        : "r"(__float_as_uint(a[0])), "r"(__float_as_uint(a[1])),
          "r"(__float_as_uint(a[2])), "r"(__float_as_uint(a[3])),
          "r"(__float_as_uint(b[0])), "r"(__float_as_uint(b[1])));
}

// permuted column position within 8-groups: p=(c&3)*2+(c>>2)
__device__ __forceinline__ int dperm(int c) {
    int inner = c & 7;
    return (c & ~7) + ((inner & 3) * 2) + (inner >> 2);
}
// inverse: logical column stored at physical p
__device__ __forceinline__ int invperm(int p) {
    int inner = p & 7;
    return (p & ~7) + ((inner & 1) * 4) + (inner >> 1);
}

// ============================================================================
// init
// ============================================================================
__global__ void init_kernel(const float* __restrict__ cluster_size,
                            const float* __restrict__ embed_avg,
                            float* __restrict__ cs_out,
                            float* __restrict__ avg_out) {
    int t = blockIdx.x * blockDim.x + threadIdx.x;
    if (t < NK) cs_out[t] = 0.99f * cluster_size[t];
    if (t < NK * DD) avg_out[t] = 0.99f * embed_avg[t];
    if (t == 0) { g_maxBlBits = 0; g_flagCnt = 0; }
}

// ============================================================================
// Row L2-normalize (final new_embedding). One warp per row.
// ============================================================================
__global__ void norm_rows_kernel(const float* __restrict__ in,
                                 float* __restrict__ out, int nrows) {
    int warp = (blockIdx.x * blockDim.x + threadIdx.x) >> 5;
    int lane = threadIdx.x & 31;
    if (warp >= nrows) return;
    const float4* ip = reinterpret_cast<const float4*>(in + (size_t)warp * DD);
    float4 v0 = ip[lane];
    float4 v1 = ip[lane + 32];
    float s = v0.x*v0.x + v0.y*v0.y + v0.z*v0.z + v0.w*v0.w
            + v1.x*v1.x + v1.y*v1.y + v1.z*v1.z + v1.w*v1.w;
    #pragma unroll
    for (int off = 16; off > 0; off >>= 1) s += __shfl_xor_sync(0xFFFFFFFFu, s, off);
    float nrm = fmaxf(sqrtf(s), 1e-12f);
    float4 o0, o1;
    o0.x = v0.x/nrm; o0.y = v0.y/nrm; o0.z = v0.z/nrm; o0.w = v0.w/nrm;
    o1.x = v1.x/nrm; o1.y = v1.y/nrm; o1.z = v1.z/nrm; o1.w = v1.w/nrm;
    float4* op = reinterpret_cast<float4*>(out + (size_t)warp * DD);
    op[lane] = o0; op[lane + 32] = o1;
}

// ============================================================================
// normalize codebook rows + exact tf32 split (permuted) + max ||bl||.
// ============================================================================
__global__ void norm_split_embed(const float* __restrict__ in) {
    int warp = (blockIdx.x * blockDim.x + threadIdx.x) >> 5;
    int lane = threadIdx.x & 31;
    if (warp >= NK) return;
    const float4* ip = reinterpret_cast<const float4*>(in + (size_t)warp * DD);
    float4 v0 = ip[lane];
    float4 v1 = ip[lane + 32];
    float s = v0.x*v0.x + v0.y*v0.y + v0.z*v0.z + v0.w*v0.w
            + v1.x*v1.x + v1.y*v1.y + v1.z*v1.z + v1.w*v1.w;
    #pragma unroll
    for (int off = 16; off > 0; off >>= 1) s += __shfl_xor_sync(0xFFFFFFFFu, s, off);
    float inv = 1.0f / fmaxf(sqrtf(s), 1e-12f);
    float vv[8] = {v0.x, v0.y, v0.z, v0.w, v1.x, v1.y, v1.z, v1.w};
    float bl2 = 0.0f;
    #pragma unroll
    for (int i = 0; i < 8; i++) {
        int c = (i < 4) ? (lane * 4 + i) : (128 + lane * 4 + (i - 4));
        float v = vv[i] * inv;
        float h = tf32_rna(v);
        float l = v - h;
        int dp = dperm(c);
        g_Bhi[(size_t)warp * DD + dp] = h;
        g_Blo[(size_t)warp * DD + dp] = l;
        bl2 += l * l;
    }
    #pragma unroll
    for (int off = 16; off > 0; off >>= 1) bl2 += __shfl_xor_sync(0xFFFFFFFFu, bl2, off);
    if (lane == 0) atomicMax(&g_maxBlBits, __float_as_int(sqrtf(bl2)));
}

// ============================================================================
// Transpose z -> token-major, exact tf32 split (permuted). Pure transform.
// ============================================================================
__global__ void transpose_split(const float* __restrict__ z) {
    __shared__ float t[32][33];
    int tx = threadIdx.x, ty = threadIdx.y;
    int hw0 = blockIdx.x * 32, d0 = blockIdx.y * 32, b = blockIdx.z;
    const float* zb = z + (size_t)b * DD * HWSZ;
    #pragma unroll
    for (int i = 0; i < 4; i++) {
        int d = d0 + ty + i * 8;
        t[ty + i * 8][tx] = zb[(size_t)d * HWSZ + hw0 + tx];
    }
    __syncthreads();
    int dp = d0 + dperm(tx);
    #pragma unroll
    for (int i = 0; i < 4; i++) {
        int hwl = ty + i * 8;
        int n = b * HWSZ + hw0 + hwl;
        float v = t[tx][hwl];
        float h = tf32_rna(v);
        float l = v - h;
        g_Ahi[(size_t)n * DD + dp] = h;
        g_Alo[(size_t)n * DD + dp] = l;
    }
}

// ============================================================================
// Per-token ||ah||^2 / ||al||^2: warp per token, coalesced float4 rows.
// ============================================================================
__global__ void norm_tokens() {
    int warp = (blockIdx.x * blockDim.x + threadIdx.x) >> 5;
    int lane = threadIdx.x & 31;
    if (warp >= NTOK) return;
    const float4* hp = reinterpret_cast<const float4*>(g_Ahi + (size_t)warp * DD);
    const float4* lp = reinterpret_cast<const float4*>(g_Alo + (size_t)warp * DD);
    float4 h0 = hp[lane], h1 = hp[lane + 32];
    float4 l0 = lp[lane], l1 = lp[lane + 32];
    float sh = h0.x*h0.x + h0.y*h0.y + h0.z*h0.z + h0.w*h0.w
             + h1.x*h1.x + h1.y*h1.y + h1.z*h1.z + h1.w*h1.w;
    float sl = l0.x*l0.x + l0.y*l0.y + l0.z*l0.z + l0.w*l0.w
             + l1.x*l1.x + l1.y*l1.y + l1.z*l1.z + l1.w*l1.w;
    #pragma unroll
    for (int off = 16; off > 0; off >>= 1) {
        sh += __shfl_xor_sync(0xFFFFFFFFu, sh, off);
        sl += __shfl_xor_sync(0xFFFFFFFFu, sl, off);
    }
    if (lane == 0) { g_nAh2[warp] = sh; g_nAl2[warp] = sl; }
}

// ============================================================================
// Coarse GEMM (R7/R11-proven): 64 tok x 1024 codes, 128 thr, warptile 64x32,
// 4 CTAs/SM, 3-stage cp.async pipeline, ONE __syncthreads per iter.
// ============================================================================
#define CW3    24
#define ABUF3  6144            // 64*24*4
#define BBUF3  12288           // 128*24*4
#define STG3   (ABUF3+BBUF3)   // 18432
#define GSM4   (3*STG3)        // 55296

__global__ __launch_bounds__(128, 4) void coarse_gemm() {
    extern __shared__ float sm[];
    const uint32_t sbase = smem_to_u32(sm);
    const int tid  = threadIdx.x;
    const int wc   = tid >> 5;
    const int lane = tid & 31;
    const int g  = lane >> 2;
    const int tg = lane & 3;

    const int tile    = blockIdx.x >> 3;
    const int slice   = blockIdx.x & 7;
    const int rowBase = tile * 64;
    const int kBase   = slice * KSLICE;

    float acc[4][4][4];
    #pragma unroll
    for (int mt = 0; mt < 4; mt++)
        #pragma unroll
        for (int nt = 0; nt < 4; nt++)
            #pragma unroll
            for (int q = 0; q < 4; q++) acc[mt][nt][q] = 0.0f;

    float bestV[8], secV[8];
    int   bestI[8];
    #pragma unroll
    for (int s = 0; s < 8; s++) {
        bestV[s] = -INFINITY; secV[s] = -INFINITY; bestI[s] = 0x7fffffff;
    }

    const int rA = tid >> 2;
    const int cA = tid & 3;
    const float* pA[2];
    const float* pB[4];
    uint32_t offA[2], offB[4];
    #pragma unroll
    for (int j = 0; j < 2; j++) {
        pA[j]   = g_Ahi + ((size_t)(rowBase + rA + 32 * j) * DD + cA * 4);
        offA[j] = (uint32_t)((rA + 32 * j) * 96 + cA * 16);
    }
    #pragma unroll
    for (int j = 0; j < 4; j++) {
        pB[j]   = g_Bhi + ((size_t)(kBase + rA + 32 * j) * DD + cA * 4);
        offB[j] = (uint32_t)(ABUF3 + (rA + 32 * j) * 96 + cA * 16);
    }
    int ldj = 0;
    auto load = [&](uint32_t sb) {
        cpasync16(sb + offA[0], pA[0]);
        cpasync16(sb + offA[1], pA[1]);
        #pragma unroll
        for (int j = 0; j < 4; j++) cpasync16(sb + offB[j], pB[j]);
        CPASYNC_COMMIT();
        int wrap = ((ldj & 15) == 15);
        ldj++;
        int dA = wrap ? (16 - 256) : 16;
        int dB = wrap ? (16 - 256 + 128 * DD) : 16;
        pA[0] += dA; pA[1] += dA;
        #pragma unroll
        for (int j = 0; j < 4; j++) pB[j] += dB;
    };

    const uint32_t stB0 = sbase, stB1 = sbase + STG3, stB2 = sbase + 2 * STG3;
    load(stB0); load(stB1);
    CPASYNC_WAIT(1);
    __syncthreads();

    int stg = 0;
    uint32_t stNext = stB2;
    for (int it = 0; it < 128; it++) {
        if (it < 126) load(stNext);

        const float* Ah = sm + stg * (STG3 / 4);
        const float* Bh = Ah + (ABUF3 / 4);

        #pragma unroll
        for (int ks = 0; ks < 2; ks++) {
            int kp = ks * 8 + 2 * tg;
            float2 af[4][2], bf[4];
            #pragma unroll
            for (int mt = 0; mt < 4; mt++) {
                const float* p = Ah + (mt * 16 + g) * CW3 + kp;
                af[mt][0] = *(const float2*)p;
                af[mt][1] = *(const float2*)(p + 8 * CW3);
            }
            #pragma unroll
            for (int nt = 0; nt < 4; nt++)
                bf[nt] = *(const float2*)(Bh + (wc * 32 + nt * 8 + g) * CW3 + kp);
            #pragma unroll
            for (int mt = 0; mt < 4; mt++)
                #pragma unroll
                for (int nt = 0; nt < 4; nt++) {
                    float a[4] = {af[mt][0].x, af[mt][1].x, af[mt][0].y, af[mt][1].y};
                    float b[2] = {bf[nt].x, bf[nt].y};
                    mma8(acc[mt][nt], a, b);
                }
        }

        if ((it & 15) == 15) {
            int colBase = kBase + (it >> 4) * 128 + wc * 32;
            #pragma unroll
            for (int mt = 0; mt < 4; mt++)
                #pragma unroll
                for (int half = 0; half < 2; half++) {
                    int slot = mt * 2 + half;
                    float v[8];
                    #pragma unroll
                    for (int nt = 0; nt < 4; nt++)
                        #pragma unroll
                        for (int j = 0; j < 2; j++)
                            v[nt * 2 + j] = acc[mt][nt][half * 2 + j];
                    float m01 = fmaxf(v[0], v[1]), m23 = fmaxf(v[2], v[3]);
                    float m45 = fmaxf(v[4], v[5]), m67 = fmaxf(v[6], v[7]);
                    float m1  = fmaxf(fmaxf(m01, m23), fmaxf(m45, m67));
                    if (m1 > bestV[slot]) {
                        secV[slot] = fmaxf(secV[slot], bestV[slot]);
                        int bi = 0x7fffffff;
                        #pragma unroll
                        for (int q = 0; q < 8; q++)
                            if (v[q] == m1) bi = min(bi, colBase + (q >> 1) * 8 + tg * 2 + (q & 1));
                        float m2 = -INFINITY;
                        #pragma unroll
                        for (int q = 0; q < 8; q++) {
                            int cq = colBase + (q >> 1) * 8 + tg * 2 + (q & 1);
                            m2 = fmaxf(m2, (cq == bi) ? -INFINITY : v[q]);
                        }
                        bestV[slot] = m1;
                        bestI[slot] = bi;
                        secV[slot]  = fmaxf(secV[slot], m2);
                    } else {
                        secV[slot] = fmaxf(secV[slot], m1);
                    }
                }
            #pragma unroll
            for (int mt = 0; mt < 4; mt++)
                #pragma unroll
                for (int nt = 0; nt < 4; nt++)
                    #pragma unroll
                    for (int q = 0; q < 4; q++) acc[mt][nt][q] = 0.0f;
        }

        if (it < 126) CPASYNC_WAIT(1);
        else          CPASYNC_WAIT(0);
        __syncthreads();

        stg++; if (stg == 3) stg = 0;
        stNext += STG3; if (stNext > stB2) stNext = stB0;
    }

    // cross-thread merge: 16 contributors (wc x tg) per row, 64 rows
    float* sv1 = sm;
    int*   si1 = (int*)(sm + 1024);
    float* sv2 = sm + 2048;
    #pragma unroll
    for (int slot = 0; slot < 8; slot++) {
        int row = (slot >> 1) * 16 + (slot & 1) * 8 + g;
        int ent = row * 16 + wc * 4 + tg;
        sv1[ent] = bestV[slot];
        si1[ent] = bestI[slot];
        sv2[ent] = secV[slot];
    }
    __syncthreads();
    if (tid < 64) {
        float V1 = -INFINITY, V2 = -INFINITY;
        int I1 = 0x7fffffff;
        #pragma unroll
        for (int t = 0; t < 16; t++) {
            float v1 = sv1[tid * 16 + t];
            int   i1 = si1[tid * 16 + t];
            float v2 = sv2[tid * 16 + t];
            if (v1 > V1 || (v1 == V1 && i1 < I1)) {
                V2 = fmaxf(fmaxf(V2, V1), v2);
                V1 = v1; I1 = i1;
            } else {
                V2 = fmaxf(V2, v1);
            }
        }
        size_t e = (size_t)blockIdx.x * 64 + tid;
        g_pv[e] = make_float2(V1, V2);
        g_pi[e] = I1;
    }
}

// ============================================================================
// Merge slices + rigorous margin test; flag uncertain tokens. (64-row tiles)
// ============================================================================
__global__ void merge_kernel() {
    int n = blockIdx.x * blockDim.x + threadIdx.x;
    if (n >= NTOK) return;
    int tile = n >> 6, row = n & 63;
    float V1 = -INFINITY, V2 = -INFINITY;
    int I1 = 0x7fffffff;
    #pragma unroll
    for (int s = 0; s < NSLICE; s++) {
        size_t e = ((size_t)(tile * NSLICE + s)) * 64 + row;
        float2 v = g_pv[e];
        int   i1 = g_pi[e];
        if (v.x > V1 || (v.x == V1 && i1 < I1)) {
            V2 = fmaxf(fmaxf(V2, V1), v.y);
            V1 = v.x; I1 = i1;
        } else {
            V2 = fmaxf(V2, v.x);
        }
    }
    float maxBl = __int_as_float(g_maxBlBits);
    float nAh = sqrtf(g_nAh2[n]);
    float nAl = sqrtf(g_nAl2[n]);
    float margin = nAl * 1.0001f + nAh * (maxBl + 5e-5f);
    if (V1 - V2 >= 2.0f * margin) {
        g_idx[n] = I1;
    } else {
        int s = atomicAdd(&g_flagCnt, 1);
        g_flagTok[s] = n;
        g_idx[n] = I1;
    }
}

// ============================================================================
// 3xTF32 tensor-core rescore (R7-proven version).
// ============================================================================
#define RABUF  6144                 // Ah 64x24x4 (Al at +RABUF)
#define RBBUF  12288                // Bh 128x24x4
#define RBOFF  (2*RABUF)            // Bh base (Bl at +RBBUF)
#define RSTG   (2*RABUF + 2*RBBUF)  // 36864
#define RGSM   (2*RSTG)             // 73728

__global__ __launch_bounds__(128, 2) void rescore_mma() {
    extern __shared__ float sm[];
    const uint32_t sbase = smem_to_u32(sm);
    __shared__ int toks[64];
    int count = g_flagCnt;
    const int tile  = blockIdx.x >> 3;
    const int slice = blockIdx.x & 7;
    const int base  = tile * 64;
    if (base >= count) return;
    const int tid  = threadIdx.x;
    const int wc   = tid >> 5;
    const int lane = tid & 31;
    const int g  = lane >> 2;
    const int tg = lane & 3;
    const int kBase = slice * KSLICE;

    if (tid < 64) toks[tid] = (base + tid < count) ? g_flagTok[base + tid] : g_flagTok[0];
    __syncthreads();

    const ptrdiff_t ALO = g_Alo - g_Ahi;
    const ptrdiff_t BLO = g_Blo - g_Bhi;

    const int rA = tid >> 2;
    const int cA = tid & 3;
    const float* pA[2];
    const float* pB[4];
    uint32_t offA[2], offB[4];
    #pragma unroll
    for (int j = 0; j < 2; j++) {
        pA[j]   = g_Ahi + ((size_t)toks[rA + 32 * j] * DD + cA * 4);
        offA[j] = (uint32_t)((rA + 32 * j) * 96 + cA * 16);
    }
    #pragma unroll
    for (int j = 0; j < 4; j++) {
        pB[j]   = g_Bhi + ((size_t)(kBase + rA + 32 * j) * DD + cA * 4);
        offB[j] = (uint32_t)(RBOFF + (rA + 32 * j) * 96 + cA * 16);
    }
    int ldj = 0;
    auto load = [&](uint32_t sb) {
        #pragma unroll
        for (int j = 0; j < 2; j++) {
            cpasync16(sb + offA[j],         pA[j]);
            cpasync16(sb + offA[j] + RABUF, pA[j] + ALO);
        }
        #pragma unroll
        for (int j = 0; j < 4; j++) {
            cpasync16(sb + offB[j],         pB[j]);
            cpasync16(sb + offB[j] + RBBUF, pB[j] + BLO);
        }
        CPASYNC_COMMIT();
        int wrap = ((ldj & 15) == 15);
        ldj++;
        int dA = wrap ? (16 - 256) : 16;
        int dB = wrap ? (16 - 256 + 128 * DD) : 16;
        pA[0] += dA; pA[1] += dA;
        #pragma unroll
        for (int j = 0; j < 4; j++) pB[j] += dB;
    };

    float acc[4][4][4];
    #pragma unroll
    for (int mt = 0; mt < 4; mt++)
        #pragma unroll
        for (int nt = 0; nt < 4; nt++)
            #pragma unroll
            for (int q = 0; q < 4; q++) acc[mt][nt][q] = 0.0f;

    float bestV[8];
    int   bestI[8];
    #pragma unroll
    for (int s = 0; s < 8; s++) { bestV[s] = -INFINITY; bestI[s] = 0x7fffffff; }

    load(sbase);
    CPASYNC_WAIT(0);
    __syncthreads();

    for (int it = 0; it < 128; it++) {
        int stg = it & 1;
        if (it < 127) load(sbase + ((it + 1) & 1) * RSTG);

        const float* Ah = sm + stg * (RSTG / 4);
        const float* Al = Ah + (RABUF / 4);
        const float* Bh = Ah + (RBOFF / 4);
        const float* Bl = Bh + (RBBUF / 4);

        #pragma unroll
        for (int ks = 0; ks < 2; ks++) {
            int kp = ks * 8 + 2 * tg;
            float2 ah[4][2], al[4][2], bh[4], bl[4];
            #pragma unroll
            for (int mt = 0; mt < 4; mt++) {
                int ro = (mt * 16 + g) * CW3 + kp;
                ah[mt][0] = *(const float2*)(Ah + ro);
                ah[mt][1] = *(const float2*)(Ah + ro + 8 * CW3);
                al[mt][0] = *(const float2*)(Al + ro);
                al[mt][1] = *(const float2*)(Al + ro + 8 * CW3);
            }
            #pragma unroll
            for (int nt = 0; nt < 4; nt++) {
                int co = (wc * 32 + nt * 8 + g) * CW3 + kp;
                bh[nt] = *(const float2*)(Bh + co);
                bl[nt] = *(const float2*)(Bl + co);
            }
            #pragma unroll
            for (int mt = 0; mt < 4; mt++)
                #pragma unroll
                for (int nt = 0; nt < 4; nt++) {
                    float ahr[4] = {ah[mt][0].x, ah[mt][1].x, ah[mt][0].y, ah[mt][1].y};
                    float alr[4] = {al[mt][0].x, al[mt][1].x, al[mt][0].y, al[mt][1].y};
                    float bhr[2] = {bh[nt].x, bh[nt].y};
                    float blr[2] = {bl[nt].x, bl[nt].y};
                    mma8(acc[mt][nt], ahr, bhr);
                    mma8(acc[mt][nt], ahr, blr);
                    mma8(acc[mt][nt], alr, bhr);
                }
        }

        if ((it & 15) == 15) {
            int colBase = kBase + (it >> 4) * 128 + wc * 32;
            #pragma unroll
            for (int mt = 0; mt < 4; mt++)
                #pragma unroll
                for (int half = 0; half < 2; half++) {
                    int slot = mt * 2 + half;
                    float v[8];
                    #pragma unroll
                    for (int nt = 0; nt < 4; nt++)
                        #pragma unroll
                        for (int j = 0; j < 2; j++)
                            v[nt * 2 + j] = acc[mt][nt][half * 2 + j];
                    float m01 = fmaxf(v[0], v[1]), m23 = fmaxf(v[2], v[3]);
                    float m45 = fmaxf(v[4], v[5]), m67 = fmaxf(v[6], v[7]);
                    float m1  = fmaxf(fmaxf(m01, m23), fmaxf(m45, m67));
                    if (m1 > bestV[slot]) {
                        int bi = 0x7fffffff;
                        #pragma unroll
                        for (int q = 0; q < 8; q++)
                            if (v[q] == m1) bi = min(bi, colBase + (q >> 1) * 8 + tg * 2 + (q & 1));
                        bestV[slot] = m1;
                        bestI[slot] = bi;
                    }
                }
            #pragma unroll
            for (int mt = 0; mt < 4; mt++)
                #pragma unroll
                for (int nt = 0; nt < 4; nt++)
                    #pragma unroll
                    for (int q = 0; q < 4; q++) acc[mt][nt][q] = 0.0f;
        }

        CPASYNC_WAIT(0);
        __syncthreads();
    }

    // cross-thread merge: 16 contributors per row, 64 rows
    float* sv = sm;
    int*   si = (int*)(sm + 1024);
    #pragma unroll
    for (int slot = 0; slot < 8; slot++) {
        int row = (slot >> 1) * 16 + (slot & 1) * 8 + g;
        int ent = row * 16 + wc * 4 + tg;
        sv[ent] = bestV[slot];
        si[ent] = bestI[slot];
    }
    __syncthreads();
    if (tid < 64 && base + tid < count) {
        float bv = sv[tid * 16];
        int   bi = si[tid * 16];
        #pragma unroll
        for (int t = 1; t < 16; t++) {
            float v = sv[tid * 16 + t];
            int  id = si[tid * 16 + t];
            if (v > bv || (v == bv && id < bi)) { bv = v; bi = id; }
        }
        g_rv[(size_t)(base + tid) * 8 + slice] = bv;
        g_ri[(size_t)(base + tid) * 8 + slice] = bi;
    }
}

// ============================================================================
// merge2: fold 8 slice partials for flagged tokens
// ============================================================================
__global__ void merge2_kernel() {
    int slot = blockIdx.x * blockDim.x + threadIdx.x;
    if (slot >= g_flagCnt || slot >= NTOK) return;
    float bv = -INFINITY; int bi = 0x7fffffff;
    #pragma unroll
    for (int s = 0; s < 8; s++) {
        float v = g_rv[(size_t)slot * 8 + s];
        int   i = g_ri[(size_t)slot * 8 + s];
        if (v > bv || (v == bv && i < bi)) { bv = v; bi = i; }
    }
    g_idx[g_flagTok[slot]] = bi;
}

// ============================================================================
// finishA: warp per token. Coalesced embedding-row gather, exact v from
// Ahi+Alo (Sterbenz-exact split), token-major zq/zst staging, row-contiguous
// EMA atomics, cs + idx.
// ============================================================================
__global__ void finishA_kernel(const float* __restrict__ embedding,
                               float* __restrict__ avg_out,
                               float* __restrict__ cs_out,
                               float* __restrict__ idxf) {
    int warp = (blockIdx.x * blockDim.x + threadIdx.x) >> 5;
    int lane = threadIdx.x & 31;
    if (warp >= NTOK) return;
    int id = __ldg(&g_idx[warp]);
    if (lane == 0) {
        atomicAdd(&cs_out[id], 0.01f);
        idxf[warp] = (float)id;
    }
    const float* hp = g_Ahi + (size_t)warp * DD;
    const float* lp = g_Alo + (size_t)warp * DD;
    const float* er = embedding + (size_t)id * DD;
    float* avr = avg_out + (size_t)id * DD;
    float* zqr  = g_zqT  + (size_t)warp * DD;
    float* zstr = g_zstT + (size_t)warp * DD;
    #pragma unroll
    for (int half = 0; half < 2; half++) {
        int pb = half * 128 + lane * 4;
        float4 h4 = *(const float4*)(hp + pb);
        float4 l4 = *(const float4*)(lp + pb);
        float hv[4] = {h4.x, h4.y, h4.z, h4.w};
        float lv[4] = {l4.x, l4.y, l4.z, l4.w};
        #pragma unroll
        for (int j = 0; j < 4; j++) {
            int p = pb + j;
            int c = invperm(p);
            float v = hv[j] + lv[j];
            float e = __ldg(er + c);
            zqr[c]  = e;
            zstr[c] = v + (e - v);
            atomicAdd(avr + c, 0.01f * v);
        }
    }
}

// ============================================================================
// finishB: transpose token-major staging -> (B,D,H,W) outputs. Fully coalesced.
// ============================================================================
__global__ void finishB_kernel(float* __restrict__ zst,
                               float* __restrict__ zq) {
    __shared__ float tq[32][33];
    __shared__ float ts[32][33];
    int tx = threadIdx.x, ty = threadIdx.y;
    int hw0 = blockIdx.x * 32, d0 = blockIdx.y * 32, b = blockIdx.z;
    // load: rows = hw (token), cols = d (fast)
    #pragma unroll
    for (int i = 0; i < 4; i++) {
        int hwl = ty + i * 8;
        size_t o = ((size_t)(b * HWSZ + hw0 + hwl)) * DD + d0 + tx;
        tq[hwl][tx] = g_zqT[o];
        ts[hwl][tx] = g_zstT[o];
    }
    __syncthreads();
    // store: rows = d, cols = hw (fast)
    float* zqb  = zq  + (size_t)b * DD * HWSZ;
    float* zstb = zst + (size_t)b * DD * HWSZ;
    #pragma unroll
    for (int i = 0; i < 4; i++) {
        int dl = ty + i * 8;
        size_t o = (size_t)(d0 + dl) * HWSZ + hw0 + tx;
        zqb[o]  = tq[tx][dl];
        zstb[o] = ts[tx][dl];
    }
}

// ============================================================================
extern "C" void kernel_launch(void* const* d_in, const int* in_sizes, int n_in,
                              void* d_out, int out_size) {
    const float* z            = (const float*)d_in[0];
    const float* embedding    = (const float*)d_in[1];
    const float* cluster_size = (const float*)d_in[2];
    const float* embed_avg    = (const float*)d_in[3];

    float* out   = (float*)d_out;
    float* zst_o = out + OFF_ZST;
    float* idx_o = out + OFF_IDX;
    float* zq_o  = out + OFF_ZQ;
    float* emb_o = out + OFF_EMB;
    float* cs_o  = out + OFF_CS;
    float* avg_o = out + OFF_AVG;

    init_kernel<<<(NK * DD + 255) / 256, 256>>>(cluster_size, embed_avg, cs_o, avg_o);

    norm_split_embed<<<NK / 8, 256>>>(embedding);
    transpose_split<<<dim3(HWSZ / 32, DD / 32, 8), dim3(32, 8)>>>(z);
    norm_tokens<<<NTOK / 8, 256>>>();

    static bool attr_set = false;
    if (!attr_set) {
        cudaFuncSetAttribute(coarse_gemm,
                             cudaFuncAttributeMaxDynamicSharedMemorySize, GSM4);
        cudaFuncSetAttribute(rescore_mma,
                             cudaFuncAttributeMaxDynamicSharedMemorySize, RGSM);
        attr_set = true;
    }
    coarse_gemm<<<NTILE64 * NSLICE, 128, GSM4>>>();

    merge_kernel<<<NTOK / 256, 256>>>();

    rescore_mma<<<(NTOK / 64) * 8, 128, RGSM>>>();

    merge2_kernel<<<NTOK / 256, 256>>>();

    finishA_kernel<<<NTOK / 8, 256>>>(embedding, avg_o, cs_o, idx_o);
    finishB_kernel<<<dim3(HWSZ / 32, DD / 32, 8), dim3(32, 8)>>>(zst_o, zq_o);

    norm_rows_kernel<<<NK / 8, 256>>>(avg_o, emb_o, NK);
}

// round 15
// speedup vs baseline: 1.1214x; 1.0827x over previous
#include <cuda_runtime.h>
#include <cuda_bf16.h>
#include <math.h>
#include <stdint.h>

// Problem constants
#define NK    8192
#define DD    256
#define NTOK  32768
#define HWSZ  4096
#define ZELEMS 8388608

// Output layout offsets (float32, reference return order)
#define OFF_ZST  0
#define OFF_IDX  8388608
#define OFF_ZQ   8421376
#define OFF_EMB  16809984
#define OFF_CS   18907136
#define OFF_AVG  18915328

#define NSLICE 8
#define KSLICE 1024
#define NTILE64 512       // NTOK / 64
#define RSLICE 16         // rescore K-slices
#define RKS    512        // codes per rescore slice

// Scratch (__device__ globals)
__device__ float g_Ahi[NTOK * DD];
__device__ float g_Alo[NTOK * DD];
__device__ float g_Bhi[NK * DD];
__device__ float g_Blo[NK * DD];
__device__ float g_nAh2[NTOK];
__device__ float g_nAl2[NTOK];
__device__ int   g_maxBlBits;
__device__ float2 g_pv[NTILE64 * NSLICE * 64];   // (V1, V2)
__device__ int    g_pi[NTILE64 * NSLICE * 64];   // I1
__device__ int   g_flagCnt;
__device__ int   g_flagTok[NTOK];
__device__ float g_rv[NTOK * RSLICE];
__device__ int   g_ri[NTOK * RSLICE];
__device__ int   g_idx[NTOK];
__device__ float g_zqT[NTOK * DD];   // token-major zq staging (logical col order)

// ============================================================================
// helpers
// ============================================================================
__device__ __forceinline__ uint32_t smem_to_u32(const void* p) {
    uint32_t a;
    asm("{ .reg .u64 t; cvta.to.shared.u64 t, %1; cvt.u32.u64 %0, t; }" : "=r"(a) : "l"(p));
    return a;
}
__device__ __forceinline__ void cpasync16(uint32_t dst, const void* src) {
    asm volatile("cp.async.cg.shared.global [%0], [%1], 16;" :: "r"(dst), "l"(src));
}
#define CPASYNC_COMMIT() asm volatile("cp.async.commit_group;" ::: "memory")
#define CPASYNC_WAIT(n)  asm volatile("cp.async.wait_group %0;" :: "n"(n) : "memory")

__device__ __forceinline__ float tf32_rna(float x) {
    uint32_t u;
    asm("cvt.rna.tf32.f32 %0, %1;" : "=r"(u) : "f"(x));
    return __uint_as_float(u);
}

__device__ __forceinline__ void mma8(float* c, const float* a, const float* b) {
    asm volatile(
        "mma.sync.aligned.m16n8k8.row.col.f32.tf32.tf32.f32 "
        "{%0,%1,%2,%3}, {%4,%5,%6,%7}, {%8,%9}, {%0,%1,%2,%3};"
        : "+f"(c[0]), "+f"(c[1]), "+f"(c[2]), "+f"(c[3])
        : "r"(__float_as_uint(a[0])), "r"(__float_as_uint(a[1])),
          "r"(__float_as_uint(a[2])), "r"(__float_as_uint(a[3])),
          "r"(__float_as_uint(b[0])), "r"(__float_as_uint(b[1])));
}

// permuted column position within 8-groups: p=(c&3)*2+(c>>2)
__device__ __forceinline__ int dperm(int c) {
    int inner = c & 7;
    return (c & ~7) + ((inner & 3) * 2) + (inner >> 2);
}
// inverse: logical column stored at physical p
__device__ __forceinline__ int invperm(int p) {
    int inner = p & 7;
    return (p & ~7) + ((inner & 1) * 4) + (inner >> 1);
}

// ============================================================================
// init
// ============================================================================
__global__ void init_kernel(const float* __restrict__ cluster_size,
                            const float* __restrict__ embed_avg,
                            float* __restrict__ cs_out,
                            float* __restrict__ avg_out) {
    int t = blockIdx.x * blockDim.x + threadIdx.x;
    if (t < NK) cs_out[t] = 0.99f * cluster_size[t];
    if (t < NK * DD) avg_out[t] = 0.99f * embed_avg[t];
    if (t == 0) { g_maxBlBits = 0; g_flagCnt = 0; }
}

// ============================================================================
// Row L2-normalize (final new_embedding). One warp per row.
// ============================================================================
__global__ void norm_rows_kernel(const float* __restrict__ in,
                                 float* __restrict__ out, int nrows) {
    int warp = (blockIdx.x * blockDim.x + threadIdx.x) >> 5;
    int lane = threadIdx.x & 31;
    if (warp >= nrows) return;
    const float4* ip = reinterpret_cast<const float4*>(in + (size_t)warp * DD);
    float4 v0 = ip[lane];
    float4 v1 = ip[lane + 32];
    float s = v0.x*v0.x + v0.y*v0.y + v0.z*v0.z + v0.w*v0.w
            + v1.x*v1.x + v1.y*v1.y + v1.z*v1.z + v1.w*v1.w;
    #pragma unroll
    for (int off = 16; off > 0; off >>= 1) s += __shfl_xor_sync(0xFFFFFFFFu, s, off);
    float nrm = fmaxf(sqrtf(s), 1e-12f);
    float4 o0, o1;
    o0.x = v0.x/nrm; o0.y = v0.y/nrm; o0.z = v0.z/nrm; o0.w = v0.w/nrm;
    o1.x = v1.x/nrm; o1.y = v1.y/nrm; o1.z = v1.z/nrm; o1.w = v1.w/nrm;
    float4* op = reinterpret_cast<float4*>(out + (size_t)warp * DD);
    op[lane] = o0; op[lane + 32] = o1;
}

// ============================================================================
// normalize codebook rows + exact tf32 split (permuted) + max ||bl||.
// ============================================================================
__global__ void norm_split_embed(const float* __restrict__ in) {
    int warp = (blockIdx.x * blockDim.x + threadIdx.x) >> 5;
    int lane = threadIdx.x & 31;
    if (warp >= NK) return;
    const float4* ip = reinterpret_cast<const float4*>(in + (size_t)warp * DD);
    float4 v0 = ip[lane];
    float4 v1 = ip[lane + 32];
    float s = v0.x*v0.x + v0.y*v0.y + v0.z*v0.z + v0.w*v0.w
            + v1.x*v1.x + v1.y*v1.y + v1.z*v1.z + v1.w*v1.w;
    #pragma unroll
    for (int off = 16; off > 0; off >>= 1) s += __shfl_xor_sync(0xFFFFFFFFu, s, off);
    float inv = 1.0f / fmaxf(sqrtf(s), 1e-12f);
    float vv[8] = {v0.x, v0.y, v0.z, v0.w, v1.x, v1.y, v1.z, v1.w};
    float bl2 = 0.0f;
    #pragma unroll
    for (int i = 0; i < 8; i++) {
        int c = (i < 4) ? (lane * 4 + i) : (128 + lane * 4 + (i - 4));
        float v = vv[i] * inv;
        float h = tf32_rna(v);
        float l = v - h;
        int dp = dperm(c);
        g_Bhi[(size_t)warp * DD + dp] = h;
        g_Blo[(size_t)warp * DD + dp] = l;
        bl2 += l * l;
    }
    #pragma unroll
    for (int off = 16; off > 0; off >>= 1) bl2 += __shfl_xor_sync(0xFFFFFFFFu, bl2, off);
    if (lane == 0) atomicMax(&g_maxBlBits, __float_as_int(sqrtf(bl2)));
}

// ============================================================================
// Transpose z -> token-major, exact tf32 split (permuted). Pure transform.
// ============================================================================
__global__ void transpose_split(const float* __restrict__ z) {
    __shared__ float t[32][33];
    int tx = threadIdx.x, ty = threadIdx.y;
    int hw0 = blockIdx.x * 32, d0 = blockIdx.y * 32, b = blockIdx.z;
    const float* zb = z + (size_t)b * DD * HWSZ;
    #pragma unroll
    for (int i = 0; i < 4; i++) {
        int d = d0 + ty + i * 8;
        t[ty + i * 8][tx] = zb[(size_t)d * HWSZ + hw0 + tx];
    }
    __syncthreads();
    int dp = d0 + dperm(tx);
    #pragma unroll
    for (int i = 0; i < 4; i++) {
        int hwl = ty + i * 8;
        int n = b * HWSZ + hw0 + hwl;
        float v = t[tx][hwl];
        float h = tf32_rna(v);
        float l = v - h;
        g_Ahi[(size_t)n * DD + dp] = h;
        g_Alo[(size_t)n * DD + dp] = l;
    }
}

// ============================================================================
// Per-token ||ah||^2 / ||al||^2: warp per token, coalesced float4 rows.
// ============================================================================
__global__ void norm_tokens() {
    int warp = (blockIdx.x * blockDim.x + threadIdx.x) >> 5;
    int lane = threadIdx.x & 31;
    if (warp >= NTOK) return;
    const float4* hp = reinterpret_cast<const float4*>(g_Ahi + (size_t)warp * DD);
    const float4* lp = reinterpret_cast<const float4*>(g_Alo + (size_t)warp * DD);
    float4 h0 = hp[lane], h1 = hp[lane + 32];
    float4 l0 = lp[lane], l1 = lp[lane + 32];
    float sh = h0.x*h0.x + h0.y*h0.y + h0.z*h0.z + h0.w*h0.w
             + h1.x*h1.x + h1.y*h1.y + h1.z*h1.z + h1.w*h1.w;
    float sl = l0.x*l0.x + l0.y*l0.y + l0.z*l0.z + l0.w*l0.w
             + l1.x*l1.x + l1.y*l1.y + l1.z*l1.z + l1.w*l1.w;
    #pragma unroll
    for (int off = 16; off > 0; off >>= 1) {
        sh += __shfl_xor_sync(0xFFFFFFFFu, sh, off);
        sl += __shfl_xor_sync(0xFFFFFFFFu, sl, off);
    }
    if (lane == 0) { g_nAh2[warp] = sh; g_nAl2[warp] = sl; }
}

// ============================================================================
// Coarse GEMM (R7/R11-proven): 64 tok x 1024 codes, 128 thr, warptile 64x32,
// 4 CTAs/SM, 3-stage cp.async pipeline, ONE __syncthreads per iter.
// ============================================================================
#define CW3    24
#define ABUF3  6144            // 64*24*4
#define BBUF3  12288           // 128*24*4
#define STG3   (ABUF3+BBUF3)   // 18432
#define GSM4   (3*STG3)        // 55296

__global__ __launch_bounds__(128, 4) void coarse_gemm() {
    extern __shared__ float sm[];
    const uint32_t sbase = smem_to_u32(sm);
    const int tid  = threadIdx.x;
    const int wc   = tid >> 5;
    const int lane = tid & 31;
    const int g  = lane >> 2;
    const int tg = lane & 3;

    const int tile    = blockIdx.x >> 3;
    const int slice   = blockIdx.x & 7;
    const int rowBase = tile * 64;
    const int kBase   = slice * KSLICE;

    float acc[4][4][4];
    #pragma unroll
    for (int mt = 0; mt < 4; mt++)
        #pragma unroll
        for (int nt = 0; nt < 4; nt++)
            #pragma unroll
            for (int q = 0; q < 4; q++) acc[mt][nt][q] = 0.0f;

    float bestV[8], secV[8];
    int   bestI[8];
    #pragma unroll
    for (int s = 0; s < 8; s++) {
        bestV[s] = -INFINITY; secV[s] = -INFINITY; bestI[s] = 0x7fffffff;
    }

    const int rA = tid >> 2;
    const int cA = tid & 3;
    const float* pA[2];
    const float* pB[4];
    uint32_t offA[2], offB[4];
    #pragma unroll
    for (int j = 0; j < 2; j++) {
        pA[j]   = g_Ahi + ((size_t)(rowBase + rA + 32 * j) * DD + cA * 4);
        offA[j] = (uint32_t)((rA + 32 * j) * 96 + cA * 16);
    }
    #pragma unroll
    for (int j = 0; j < 4; j++) {
        pB[j]   = g_Bhi + ((size_t)(kBase + rA + 32 * j) * DD + cA * 4);
        offB[j] = (uint32_t)(ABUF3 + (rA + 32 * j) * 96 + cA * 16);
    }
    int ldj = 0;
    auto load = [&](uint32_t sb) {
        cpasync16(sb + offA[0], pA[0]);
        cpasync16(sb + offA[1], pA[1]);
        #pragma unroll
        for (int j = 0; j < 4; j++) cpasync16(sb + offB[j], pB[j]);
        CPASYNC_COMMIT();
        int wrap = ((ldj & 15) == 15);
        ldj++;
        int dA = wrap ? (16 - 256) : 16;
        int dB = wrap ? (16 - 256 + 128 * DD) : 16;
        pA[0] += dA; pA[1] += dA;
        #pragma unroll
        for (int j = 0; j < 4; j++) pB[j] += dB;
    };

    const uint32_t stB0 = sbase, stB1 = sbase + STG3, stB2 = sbase + 2 * STG3;
    load(stB0); load(stB1);
    CPASYNC_WAIT(1);
    __syncthreads();

    int stg = 0;
    uint32_t stNext = stB2;
    for (int it = 0; it < 128; it++) {
        if (it < 126) load(stNext);

        const float* Ah = sm + stg * (STG3 / 4);
        const float* Bh = Ah + (ABUF3 / 4);

        #pragma unroll
        for (int ks = 0; ks < 2; ks++) {
            int kp = ks * 8 + 2 * tg;
            float2 af[4][2], bf[4];
            #pragma unroll
            for (int mt = 0; mt < 4; mt++) {
                const float* p = Ah + (mt * 16 + g) * CW3 + kp;
                af[mt][0] = *(const float2*)p;
                af[mt][1] = *(const float2*)(p + 8 * CW3);
            }
            #pragma unroll
            for (int nt = 0; nt < 4; nt++)
                bf[nt] = *(const float2*)(Bh + (wc * 32 + nt * 8 + g) * CW3 + kp);
            #pragma unroll
            for (int mt = 0; mt < 4; mt++)
                #pragma unroll
                for (int nt = 0; nt < 4; nt++) {
                    float a[4] = {af[mt][0].x, af[mt][1].x, af[mt][0].y, af[mt][1].y};
                    float b[2] = {bf[nt].x, bf[nt].y};
                    mma8(acc[mt][nt], a, b);
                }
        }

        if ((it & 15) == 15) {
            int colBase = kBase + (it >> 4) * 128 + wc * 32;
            #pragma unroll
            for (int mt = 0; mt < 4; mt++)
                #pragma unroll
                for (int half = 0; half < 2; half++) {
                    int slot = mt * 2 + half;
                    float v[8];
                    #pragma unroll
                    for (int nt = 0; nt < 4; nt++)
                        #pragma unroll
                        for (int j = 0; j < 2; j++)
                            v[nt * 2 + j] = acc[mt][nt][half * 2 + j];
                    float m01 = fmaxf(v[0], v[1]), m23 = fmaxf(v[2], v[3]);
                    float m45 = fmaxf(v[4], v[5]), m67 = fmaxf(v[6], v[7]);
                    float m1  = fmaxf(fmaxf(m01, m23), fmaxf(m45, m67));
                    if (m1 > bestV[slot]) {
                        secV[slot] = fmaxf(secV[slot], bestV[slot]);
                        int bi = 0x7fffffff;
                        #pragma unroll
                        for (int q = 0; q < 8; q++)
                            if (v[q] == m1) bi = min(bi, colBase + (q >> 1) * 8 + tg * 2 + (q & 1));
                        float m2 = -INFINITY;
                        #pragma unroll
                        for (int q = 0; q < 8; q++) {
                            int cq = colBase + (q >> 1) * 8 + tg * 2 + (q & 1);
                            m2 = fmaxf(m2, (cq == bi) ? -INFINITY : v[q]);
                        }
                        bestV[slot] = m1;
                        bestI[slot] = bi;
                        secV[slot]  = fmaxf(secV[slot], m2);
                    } else {
                        secV[slot] = fmaxf(secV[slot], m1);
                    }
                }
            #pragma unroll
            for (int mt = 0; mt < 4; mt++)
                #pragma unroll
                for (int nt = 0; nt < 4; nt++)
                    #pragma unroll
                    for (int q = 0; q < 4; q++) acc[mt][nt][q] = 0.0f;
        }

        if (it < 126) CPASYNC_WAIT(1);
        else          CPASYNC_WAIT(0);
        __syncthreads();

        stg++; if (stg == 3) stg = 0;
        stNext += STG3; if (stNext > stB2) stNext = stB0;
    }

    // cross-thread merge: 16 contributors (wc x tg) per row, 64 rows
    float* sv1 = sm;
    int*   si1 = (int*)(sm + 1024);
    float* sv2 = sm + 2048;
    #pragma unroll
    for (int slot = 0; slot < 8; slot++) {
        int row = (slot >> 1) * 16 + (slot & 1) * 8 + g;
        int ent = row * 16 + wc * 4 + tg;
        sv1[ent] = bestV[slot];
        si1[ent] = bestI[slot];
        sv2[ent] = secV[slot];
    }
    __syncthreads();
    if (tid < 64) {
        float V1 = -INFINITY, V2 = -INFINITY;
        int I1 = 0x7fffffff;
        #pragma unroll
        for (int t = 0; t < 16; t++) {
            float v1 = sv1[tid * 16 + t];
            int   i1 = si1[tid * 16 + t];
            float v2 = sv2[tid * 16 + t];
            if (v1 > V1 || (v1 == V1 && i1 < I1)) {
                V2 = fmaxf(fmaxf(V2, V1), v2);
                V1 = v1; I1 = i1;
            } else {
                V2 = fmaxf(V2, v1);
            }
        }
        size_t e = (size_t)blockIdx.x * 64 + tid;
        g_pv[e] = make_float2(V1, V2);
        g_pi[e] = I1;
    }
}

// ============================================================================
// Merge slices + rigorous margin test; flag uncertain tokens. (64-row tiles)
// ============================================================================
__global__ void merge_kernel() {
    int n = blockIdx.x * blockDim.x + threadIdx.x;
    if (n >= NTOK) return;
    int tile = n >> 6, row = n & 63;
    float V1 = -INFINITY, V2 = -INFINITY;
    int I1 = 0x7fffffff;
    #pragma unroll
    for (int s = 0; s < NSLICE; s++) {
        size_t e = ((size_t)(tile * NSLICE + s)) * 64 + row;
        float2 v = g_pv[e];
        int   i1 = g_pi[e];
        if (v.x > V1 || (v.x == V1 && i1 < I1)) {
            V2 = fmaxf(fmaxf(V2, V1), v.y);
            V1 = v.x; I1 = i1;
        } else {
            V2 = fmaxf(V2, v.x);
        }
    }
    float maxBl = __int_as_float(g_maxBlBits);
    float nAh = sqrtf(g_nAh2[n]);
    float nAl = sqrtf(g_nAl2[n]);
    float margin = nAl * 1.0001f + nAh * (maxBl + 5e-5f);
    if (V1 - V2 >= 2.0f * margin) {
        g_idx[n] = I1;
    } else {
        int s = atomicAdd(&g_flagCnt, 1);
        g_flagTok[s] = n;
        g_idx[n] = I1;
    }
}

// ============================================================================
// 3xTF32 tensor-core rescore: 16 K-slices of 512 codes (wave-balance fix).
// ============================================================================
#define RABUF  6144                 // Ah 64x24x4 (Al at +RABUF)
#define RBBUF  12288                // Bh 128x24x4
#define RBOFF  (2*RABUF)            // Bh base (Bl at +RBBUF)
#define RSTG   (2*RABUF + 2*RBBUF)  // 36864
#define RGSM   (2*RSTG)             // 73728

__global__ __launch_bounds__(128, 2) void rescore_mma() {
    extern __shared__ float sm[];
    const uint32_t sbase = smem_to_u32(sm);
    __shared__ int toks[64];
    int count = g_flagCnt;
    const int tile  = blockIdx.x >> 4;
    const int slice = blockIdx.x & 15;
    const int base  = tile * 64;
    if (base >= count) return;
    const int tid  = threadIdx.x;
    const int wc   = tid >> 5;
    const int lane = tid & 31;
    const int g  = lane >> 2;
    const int tg = lane & 3;
    const int kBase = slice * RKS;

    if (tid < 64) toks[tid] = (base + tid < count) ? g_flagTok[base + tid] : g_flagTok[0];
    __syncthreads();

    const ptrdiff_t ALO = g_Alo - g_Ahi;
    const ptrdiff_t BLO = g_Blo - g_Bhi;

    const int rA = tid >> 2;
    const int cA = tid & 3;
    const float* pA[2];
    const float* pB[4];
    uint32_t offA[2], offB[4];
    #pragma unroll
    for (int j = 0; j < 2; j++) {
        pA[j]   = g_Ahi + ((size_t)toks[rA + 32 * j] * DD + cA * 4);
        offA[j] = (uint32_t)((rA + 32 * j) * 96 + cA * 16);
    }
    #pragma unroll
    for (int j = 0; j < 4; j++) {
        pB[j]   = g_Bhi + ((size_t)(kBase + rA + 32 * j) * DD + cA * 4);
        offB[j] = (uint32_t)(RBOFF + (rA + 32 * j) * 96 + cA * 16);
    }
    int ldj = 0;
    auto load = [&](uint32_t sb) {
        #pragma unroll
        for (int j = 0; j < 2; j++) {
            cpasync16(sb + offA[j],         pA[j]);
            cpasync16(sb + offA[j] + RABUF, pA[j] + ALO);
        }
        #pragma unroll
        for (int j = 0; j < 4; j++) {
            cpasync16(sb + offB[j],         pB[j]);
            cpasync16(sb + offB[j] + RBBUF, pB[j] + BLO);
        }
        CPASYNC_COMMIT();
        int wrap = ((ldj & 15) == 15);
        ldj++;
        int dA = wrap ? (16 - 256) : 16;
        int dB = wrap ? (16 - 256 + 128 * DD) : 16;
        pA[0] += dA; pA[1] += dA;
        #pragma unroll
        for (int j = 0; j < 4; j++) pB[j] += dB;
    };

    float acc[4][4][4];
    #pragma unroll
    for (int mt = 0; mt < 4; mt++)
        #pragma unroll
        for (int nt = 0; nt < 4; nt++)
            #pragma unroll
            for (int q = 0; q < 4; q++) acc[mt][nt][q] = 0.0f;

    float bestV[8];
    int   bestI[8];
    #pragma unroll
    for (int s = 0; s < 8; s++) { bestV[s] = -INFINITY; bestI[s] = 0x7fffffff; }

    load(sbase);
    CPASYNC_WAIT(0);
    __syncthreads();

    for (int it = 0; it < 64; it++) {
        int stg = it & 1;
        if (it < 63) load(sbase + ((it + 1) & 1) * RSTG);

        const float* Ah = sm + stg * (RSTG / 4);
        const float* Al = Ah + (RABUF / 4);
        const float* Bh = Ah + (RBOFF / 4);
        const float* Bl = Bh + (RBBUF / 4);

        #pragma unroll
        for (int ks = 0; ks < 2; ks++) {
            int kp = ks * 8 + 2 * tg;
            float2 ah[4][2], al[4][2], bh[4], bl[4];
            #pragma unroll
            for (int mt = 0; mt < 4; mt++) {
                int ro = (mt * 16 + g) * CW3 + kp;
                ah[mt][0] = *(const float2*)(Ah + ro);
                ah[mt][1] = *(const float2*)(Ah + ro + 8 * CW3);
                al[mt][0] = *(const float2*)(Al + ro);
                al[mt][1] = *(const float2*)(Al + ro + 8 * CW3);
            }
            #pragma unroll
            for (int nt = 0; nt < 4; nt++) {
                int co = (wc * 32 + nt * 8 + g) * CW3 + kp;
                bh[nt] = *(const float2*)(Bh + co);
                bl[nt] = *(const float2*)(Bl + co);
            }
            #pragma unroll
            for (int mt = 0; mt < 4; mt++)
                #pragma unroll
                for (int nt = 0; nt < 4; nt++) {
                    float ahr[4] = {ah[mt][0].x, ah[mt][1].x, ah[mt][0].y, ah[mt][1].y};
                    float alr[4] = {al[mt][0].x, al[mt][1].x, al[mt][0].y, al[mt][1].y};
                    float bhr[2] = {bh[nt].x, bh[nt].y};
                    float blr[2] = {bl[nt].x, bl[nt].y};
                    mma8(acc[mt][nt], ahr, bhr);
                    mma8(acc[mt][nt], ahr, blr);
                    mma8(acc[mt][nt], alr, bhr);
                }
        }

        if ((it & 15) == 15) {
            int colBase = kBase + (it >> 4) * 128 + wc * 32;
            #pragma unroll
            for (int mt = 0; mt < 4; mt++)
                #pragma unroll
                for (int half = 0; half < 2; half++) {
                    int slot = mt * 2 + half;
                    float v[8];
                    #pragma unroll
                    for (int nt = 0; nt < 4; nt++)
                        #pragma unroll
                        for (int j = 0; j < 2; j++)
                            v[nt * 2 + j] = acc[mt][nt][half * 2 + j];
                    float m01 = fmaxf(v[0], v[1]), m23 = fmaxf(v[2], v[3]);
                    float m45 = fmaxf(v[4], v[5]), m67 = fmaxf(v[6], v[7]);
                    float m1  = fmaxf(fmaxf(m01, m23), fmaxf(m45, m67));
                    if (m1 > bestV[slot]) {
                        int bi = 0x7fffffff;
                        #pragma unroll
                        for (int q = 0; q < 8; q++)
                            if (v[q] == m1) bi = min(bi, colBase + (q >> 1) * 8 + tg * 2 + (q & 1));
                        bestV[slot] = m1;
                        bestI[slot] = bi;
                    }
                }
            #pragma unroll
            for (int mt = 0; mt < 4; mt++)
                #pragma unroll
                for (int nt = 0; nt < 4; nt++)
                    #pragma unroll
                    for (int q = 0; q < 4; q++) acc[mt][nt][q] = 0.0f;
        }

        CPASYNC_WAIT(0);
        __syncthreads();
    }

    // cross-thread merge: 16 contributors per row, 64 rows
    float* sv = sm;
    int*   si = (int*)(sm + 1024);
    #pragma unroll
    for (int slot = 0; slot < 8; slot++) {
        int row = (slot >> 1) * 16 + (slot & 1) * 8 + g;
        int ent = row * 16 + wc * 4 + tg;
        sv[ent] = bestV[slot];
        si[ent] = bestI[slot];
    }
    __syncthreads();
    if (tid < 64 && base + tid < count) {
        float bv = sv[tid * 16];
        int   bi = si[tid * 16];
        #pragma unroll
        for (int t = 1; t < 16; t++) {
            float v = sv[tid * 16 + t];
            int  id = si[tid * 16 + t];
            if (v > bv || (v == bv && id < bi)) { bv = v; bi = id; }
        }
        g_rv[(size_t)(base + tid) * RSLICE + slice] = bv;
        g_ri[(size_t)(base + tid) * RSLICE + slice] = bi;
    }
}

// ============================================================================
// merge2: fold 16 slice partials for flagged tokens
// ============================================================================
__global__ void merge2_kernel() {
    int slot = blockIdx.x * blockDim.x + threadIdx.x;
    if (slot >= g_flagCnt || slot >= NTOK) return;
    float bv = -INFINITY; int bi = 0x7fffffff;
    #pragma unroll
    for (int s = 0; s < RSLICE; s++) {
        float v = g_rv[(size_t)slot * RSLICE + s];
        int   i = g_ri[(size_t)slot * RSLICE + s];
        if (v > bv || (v == bv && i < bi)) { bv = v; bi = i; }
    }
    g_idx[g_flagTok[slot]] = bi;
}

// ============================================================================
// finishA: warp per token. Coalesced embedding-row gather, exact v from
// Ahi+Alo, zq staging, row-contiguous EMA atomics, cs + idx.
// ============================================================================
__global__ void finishA_kernel(const float* __restrict__ embedding,
                               float* __restrict__ avg_out,
                               float* __restrict__ cs_out,
                               float* __restrict__ idxf) {
    int warp = (blockIdx.x * blockDim.x + threadIdx.x) >> 5;
    int lane = threadIdx.x & 31;
    if (warp >= NTOK) return;
    int id = __ldg(&g_idx[warp]);
    if (lane == 0) {
        atomicAdd(&cs_out[id], 0.01f);
        idxf[warp] = (float)id;
    }
    const float* hp = g_Ahi + (size_t)warp * DD;
    const float* lp = g_Alo + (size_t)warp * DD;
    const float* er = embedding + (size_t)id * DD;
    float* avr = avg_out + (size_t)id * DD;
    float* zqr = g_zqT + (size_t)warp * DD;
    #pragma unroll
    for (int half = 0; half < 2; half++) {
        int pb = half * 128 + lane * 4;
        float4 h4 = *(const float4*)(hp + pb);
        float4 l4 = *(const float4*)(lp + pb);
        float hv[4] = {h4.x, h4.y, h4.z, h4.w};
        float lv[4] = {l4.x, l4.y, l4.z, l4.w};
        #pragma unroll
        for (int j = 0; j < 4; j++) {
            int p = pb + j;
            int c = invperm(p);
            float v = hv[j] + lv[j];
            zqr[c] = __ldg(er + c);
            atomicAdd(avr + c, 0.01f * v);
        }
    }
}

// ============================================================================
// finishB: transpose zq staging -> (B,D,H,W); zst computed from z (coalesced).
// ============================================================================
__global__ void finishB_kernel(const float* __restrict__ z,
                               float* __restrict__ zst,
                               float* __restrict__ zq) {
    __shared__ float tq[32][33];
    int tx = threadIdx.x, ty = threadIdx.y;
    int hw0 = blockIdx.x * 32, d0 = blockIdx.y * 32, b = blockIdx.z;
    #pragma unroll
    for (int i = 0; i < 4; i++) {
        int hwl = ty + i * 8;
        size_t o = ((size_t)(b * HWSZ + hw0 + hwl)) * DD + d0 + tx;
        tq[hwl][tx] = g_zqT[o];
    }
    __syncthreads();
    const float* zb = z + (size_t)b * DD * HWSZ;
    float* zqb  = zq  + (size_t)b * DD * HWSZ;
    float* zstb = zst + (size_t)b * DD * HWSZ;
    #pragma unroll
    for (int i = 0; i < 4; i++) {
        int dl = ty + i * 8;
        size_t o = (size_t)(d0 + dl) * HWSZ + hw0 + tx;
        float e  = tq[tx][dl];
        float zv = zb[o];
        zqb[o]  = e;
        zstb[o] = zv + (e - zv);
    }
}

// ============================================================================
extern "C" void kernel_launch(void* const* d_in, const int* in_sizes, int n_in,
                              void* d_out, int out_size) {
    const float* z            = (const float*)d_in[0];
    const float* embedding    = (const float*)d_in[1];
    const float* cluster_size = (const float*)d_in[2];
    const float* embed_avg    = (const float*)d_in[3];

    float* out   = (float*)d_out;
    float* zst_o = out + OFF_ZST;
    float* idx_o = out + OFF_IDX;
    float* zq_o  = out + OFF_ZQ;
    float* emb_o = out + OFF_EMB;
    float* cs_o  = out + OFF_CS;
    float* avg_o = out + OFF_AVG;

    init_kernel<<<(NK * DD + 255) / 256, 256>>>(cluster_size, embed_avg, cs_o, avg_o);

    norm_split_embed<<<NK / 8, 256>>>(embedding);
    transpose_split<<<dim3(HWSZ / 32, DD / 32, 8), dim3(32, 8)>>>(z);
    norm_tokens<<<NTOK / 8, 256>>>();

    static bool attr_set = false;
    if (!attr_set) {
        cudaFuncSetAttribute(coarse_gemm,
                             cudaFuncAttributeMaxDynamicSharedMemorySize, GSM4);
        cudaFuncSetAttribute(rescore_mma,
                             cudaFuncAttributeMaxDynamicSharedMemorySize, RGSM);
        attr_set = true;
    }
    coarse_gemm<<<NTILE64 * NSLICE, 128, GSM4>>>();

    merge_kernel<<<NTOK / 256, 256>>>();

    rescore_mma<<<(NTOK / 64) * RSLICE, 128, RGSM>>>();

    merge2_kernel<<<NTOK / 256, 256>>>();

    finishA_kernel<<<NTOK / 8, 256>>>(embedding, avg_o, cs_o, idx_o);
    finishB_kernel<<<dim3(HWSZ / 32, DD / 32, 8), dim3(32, 8)>>>(z, zst_o, zq_o);

    norm_rows_kernel<<<NK / 8, 256>>>(avg_o, emb_o, NK);
}